// round 1
// baseline (speedup 1.0000x reference)
#include <cuda_runtime.h>
#include <cstdint>
#include <cstdio>

// ============================================================================
// Problem constants
//   B=32, H=512, 3H=1536, layers T: 1024,512,256,128; din: 240,2048,2048,2048
// ============================================================================

#define NB_PER_DIR 64      // recurrence blocks per direction
#define REC_THREADS 256

// ---------------- device scratch (static, no cudaMalloc allowed) -----------
__device__ float g_xzf[50331648];   // [32][1024][1536] max
__device__ float g_xzb[50331648];
__device__ float g_y0 [33554432];   // [32][1024][1024]
__device__ float g_y1 [16777216];   // [32][512][1024]
__device__ float g_h  [2 * 2 * 32 * 512];   // [parity][dir][B][H]
__device__ unsigned int g_cnt[2];
__device__ unsigned char g_mask[32 * 1024];

// ---------------- packed f32x2 helpers -------------------------------------
__device__ __forceinline__ void fma2(unsigned long long& acc,
                                     unsigned long long a, unsigned long long b) {
    asm("fma.rn.f32x2 %0, %1, %2, %0;" : "+l"(acc) : "l"(a), "l"(b));
}
__device__ __forceinline__ unsigned long long dup2(float a) {
    unsigned long long r;
    asm("mov.b64 %0, {%1, %1};" : "=l"(r) : "f"(a));
    return r;
}
__device__ __forceinline__ float lo2(unsigned long long v) {
    return __uint_as_float((unsigned int)v);
}
__device__ __forceinline__ float hi2(unsigned long long v) {
    return __uint_as_float((unsigned int)(v >> 32));
}

// ============================================================================
// Mask kernels (exactly mirror reference: row is masked iff ALL elements == 0)
// ============================================================================
__global__ void mask_in_kernel(const float* __restrict__ x,
                               unsigned char* __restrict__ mk, int rows) {
    int r = blockIdx.x * blockDim.x + threadIdx.x;
    if (r >= rows) return;
    const float4* p = (const float4*)(x + (size_t)r * 240);
    bool any = false;
    #pragma unroll 4
    for (int i = 0; i < 60; ++i) {
        float4 v = __ldg(p + i);
        any = any | (v.x != 0.f) | (v.y != 0.f) | (v.z != 0.f) | (v.w != 0.f);
        if (any) break;
    }
    mk[r] = any ? 1 : 0;
}

// pyramid row i of layer l is concat(y_prev[2i], y_prev[2i+1]) -> 2048 floats,
// contiguous in y_prev.
__global__ void mask_py_kernel(const float* __restrict__ y,
                               unsigned char* __restrict__ mk, int T, int Tprev) {
    int r = blockIdx.x * blockDim.x + threadIdx.x;
    int rows = 32 * T;
    if (r >= rows) return;
    int b = r / T, i = r - b * T;
    const float4* p = (const float4*)(y + (((size_t)b * Tprev + 2 * i) << 10));
    bool any = false;
    for (int q = 0; q < 512; ++q) {
        float4 v = __ldg(p + q);
        any = any | (v.x != 0.f) | (v.y != 0.f) | (v.z != 0.f) | (v.w != 0.f);
        if (any) break;
    }
    mk[r] = any ? 1 : 0;
}

__global__ void zero_state_kernel() {
    int i = blockIdx.x * blockDim.x + threadIdx.x;
    for (int k = i; k < 2 * 2 * 32 * 512; k += gridDim.x * blockDim.x)
        g_h[k] = 0.f;
    if (i < 2) g_cnt[i] = 0;
}

// ============================================================================
// Input-projection GEMM:  C[m][n] = sum_k A_gathered(m,k) * W[k][n] + bias[n]
//   mode 0: A = raw inputs [B][Tcur][240]
//   mode 1: A = pyramid gather from y_prev [B][Tprev][1024]
//   rev   : time reversal (for backward direction, produces scan-ordered xz)
//   Tiles: 128x128x16, 256 threads, 8x8 per thread, f32x2 FMAs.
// ============================================================================
__device__ __forceinline__ const float* arow(const float* __restrict__ A,
                                              int m, int k0, int Tcur, int Tprev,
                                              int mode, int rev) {
    int bi = m / Tcur;
    int t  = m - bi * Tcur;
    int tt = rev ? (Tcur - 1 - t) : t;
    if (mode == 0) return A + ((size_t)bi * Tcur + tt) * 240 + k0;
    int half = k0 >> 10;
    int kk   = k0 & 1023;
    return A + (((size_t)bi * Tprev + 2 * tt + half) << 10) + kk;
}

__global__ void __launch_bounds__(256, 1) gemm_xz_kernel(
    const float* __restrict__ A, const float* __restrict__ W,
    const float* __restrict__ bias, float* __restrict__ C,
    int K, int Tcur, int Tprev, int mode, int rev) {
    __shared__ float As[16][132];   // transposed A tile, padded
    __shared__ float Bs[16][128];

    const int tid = threadIdx.x;
    const int tx = tid & 15, ty = tid >> 4;
    const int m0 = blockIdx.y << 7, n0 = blockIdx.x << 7;

    const int ar = tid >> 2;          // 0..63
    const int ak = (tid & 3) << 2;    // 0,4,8,12
    const int bk = tid >> 5;          // 0..7
    const int bn = (tid & 31) << 2;   // 0..124

    const int NT = K >> 4;
    float4 a0, a1, b0v, b1v;
    {
        const float* p0 = arow(A, m0 + ar,      0, Tcur, Tprev, mode, rev) + ak;
        const float* p1 = arow(A, m0 + ar + 64, 0, Tcur, Tprev, mode, rev) + ak;
        a0  = *(const float4*)p0;
        a1  = *(const float4*)p1;
        b0v = *(const float4*)(W + (size_t)bk * 1536 + n0 + bn);
        b1v = *(const float4*)(W + (size_t)(bk + 8) * 1536 + n0 + bn);
    }

    unsigned long long acc[8][4];
    #pragma unroll
    for (int r = 0; r < 8; ++r)
        #pragma unroll
        for (int c = 0; c < 4; ++c) acc[r][c] = 0ULL;

    for (int kt = 0; kt < NT; ++kt) {
        As[ak + 0][ar]      = a0.x; As[ak + 1][ar]      = a0.y;
        As[ak + 2][ar]      = a0.z; As[ak + 3][ar]      = a0.w;
        As[ak + 0][ar + 64] = a1.x; As[ak + 1][ar + 64] = a1.y;
        As[ak + 2][ar + 64] = a1.z; As[ak + 3][ar + 64] = a1.w;
        *(float4*)&Bs[bk][bn]     = b0v;
        *(float4*)&Bs[bk + 8][bn] = b1v;
        __syncthreads();

        if (kt + 1 < NT) {
            int k0 = (kt + 1) << 4;
            const float* p0 = arow(A, m0 + ar,      k0, Tcur, Tprev, mode, rev) + ak;
            const float* p1 = arow(A, m0 + ar + 64, k0, Tcur, Tprev, mode, rev) + ak;
            a0  = *(const float4*)p0;
            a1  = *(const float4*)p1;
            b0v = *(const float4*)(W + ((size_t)k0 + bk) * 1536 + n0 + bn);
            b1v = *(const float4*)(W + ((size_t)k0 + bk + 8) * 1536 + n0 + bn);
        }

        #pragma unroll
        for (int k = 0; k < 16; ++k) {
            float4 av0 = *(const float4*)&As[k][ty << 2];
            float4 av1 = *(const float4*)&As[k][64 + (ty << 2)];
            ulonglong2 bv0 = *(const ulonglong2*)&Bs[k][tx << 2];
            ulonglong2 bv1 = *(const ulonglong2*)&Bs[k][64 + (tx << 2)];
            float aa[8] = {av0.x, av0.y, av0.z, av0.w, av1.x, av1.y, av1.z, av1.w};
            #pragma unroll
            for (int r = 0; r < 8; ++r) {
                unsigned long long ad = dup2(aa[r]);
                fma2(acc[r][0], ad, bv0.x);
                fma2(acc[r][1], ad, bv0.y);
                fma2(acc[r][2], ad, bv1.x);
                fma2(acc[r][3], ad, bv1.y);
            }
        }
        __syncthreads();
    }

    float4 bA = *(const float4*)(bias + n0 + (tx << 2));
    float4 bB = *(const float4*)(bias + n0 + 64 + (tx << 2));
    #pragma unroll
    for (int r = 0; r < 8; ++r) {
        int m = m0 + ((r < 4) ? ((ty << 2) + r) : (64 + (ty << 2) + r - 4));
        float4 o0, o1;
        o0.x = lo2(acc[r][0]) + bA.x; o0.y = hi2(acc[r][0]) + bA.y;
        o0.z = lo2(acc[r][1]) + bA.z; o0.w = hi2(acc[r][1]) + bA.w;
        o1.x = lo2(acc[r][2]) + bB.x; o1.y = hi2(acc[r][2]) + bB.y;
        o1.z = lo2(acc[r][3]) + bB.z; o1.w = hi2(acc[r][3]) + bB.w;
        float* cp = C + (size_t)m * 1536 + n0 + (tx << 2);
        *(float4*)cp        = o0;
        *(float4*)(cp + 64) = o1;
    }
}

// ============================================================================
// Recurrence: persistent flag-synced kernel.
// Grid = 128 blocks: blockIdx/64 = direction, blockIdx%64 = 8-column chunk.
// Weights (512 x 24 slice of rk) live in SMEM; hidden state (32x512) exchanged
// through L2 (double-buffered) with a per-direction release/acquire counter.
// All 128 blocks fit in one wave (1 CTA/SM @ ~113 KB SMEM) -> no deadlock.
// ============================================================================
#define REC_SMEM ((24 * 516 + 32 * 516) * 4)

__global__ void __launch_bounds__(REC_THREADS, 1) gru_rec_kernel(
    const float* __restrict__ xzf, const float* __restrict__ xzb,
    const float* __restrict__ rkf, const float* __restrict__ rkb,
    const float* __restrict__ bf,  const float* __restrict__ bb,
    const unsigned char* __restrict__ mask,
    float* __restrict__ y, int T, int writeHidden, float* __restrict__ hiddenOut) {
    extern __shared__ float sm[];
    float* sh_w = sm;               // [24][516]  (g*8+c)*516 + k
    float* sh_h = sm + 24 * 516;    // [32][516]

    const int tid = threadIdx.x;
    const int dir = blockIdx.x >> 6;
    const int j   = blockIdx.x & 63;
    const int cb  = j << 3;
    const int b   = tid >> 3;       // batch 0..31
    const int c8  = tid & 7;        // column-in-chunk 0..7
    const int col = cb + c8;        // hidden column 0..511

    const float* xz = dir ? xzb : xzf;
    const float* rk = dir ? rkb : rkf;
    const float* bi = (dir ? bb : bf) + 1536;   // b[1] row

    // one-time: stage weight slice into SMEM (column gather)
    for (int idx = tid; idx < 512 * 24; idx += REC_THREADS) {
        int k  = idx / 24;
        int gc = idx - k * 24;
        sh_w[gc * 516 + k] = __ldg(rk + (size_t)k * 1536 + (gc >> 3) * 512 + cb + (gc & 7));
    }
    const float bz = __ldg(bi + col);
    const float br = __ldg(bi + 512 + col);
    const float bh = __ldg(bi + 1024 + col);
    __syncthreads();

    unsigned int* cnt = &g_cnt[dir];
    const float* wz = sh_w + (0 * 8 + c8) * 516;
    const float* wr = sh_w + (1 * 8 + c8) * 516;
    const float* wh = sh_w + (2 * 8 + c8) * 516;
    const float* hrow = sh_h + b * 516;

    for (int t = 0; t < T; ++t) {
        if (t > 0) {
            if (tid == 0) {
                unsigned int target = (unsigned int)(NB_PER_DIR * t);
                while (*((volatile unsigned int*)cnt) < target) { }
            }
            __syncthreads();
        }

        // prefetch xz + mask (independent of h)
        const int tsrc = dir ? (T - 1 - t) : t;
        const size_t xoff = ((size_t)b * T + t) * 1536;
        const float x0 = __ldg(xz + xoff + col);
        const float x1 = __ldg(xz + xoff + 512 + col);
        const float x2 = __ldg(xz + xoff + 1024 + col);
        const unsigned char m = mask[b * T + tsrc];

        // stage full hidden state from L2 into SMEM (skip local L1: __ldcg)
        const float* hsrc = g_h + ((((size_t)(t & 1)) * 2 + dir) << 14);
        for (int i = tid * 4; i < 32 * 512; i += REC_THREADS * 4) {
            int bb2 = i >> 9, kk = i & 511;
            float4 v = __ldcg((const float4*)(hsrc + i));
            *(float4*)(sh_h + bb2 * 516 + kk) = v;
        }
        __syncthreads();

        // 3 dot products of length 512 with packed f32x2 FMAs
        unsigned long long az = 0ULL, ar2 = 0ULL, ah = 0ULL;
        #pragma unroll 8
        for (int k = 0; k < 512; k += 4) {
            ulonglong2 h2 = *(const ulonglong2*)(hrow + k);
            ulonglong2 z2 = *(const ulonglong2*)(wz + k);
            ulonglong2 r2 = *(const ulonglong2*)(wr + k);
            ulonglong2 c2 = *(const ulonglong2*)(wh + k);
            fma2(az,  h2.x, z2.x); fma2(az,  h2.y, z2.y);
            fma2(ar2, h2.x, r2.x); fma2(ar2, h2.y, r2.y);
            fma2(ah,  h2.x, c2.x); fma2(ah,  h2.y, c2.y);
        }
        const float iz = lo2(az)  + hi2(az)  + bz;
        const float ir = lo2(ar2) + hi2(ar2) + br;
        const float ic = lo2(ah)  + hi2(ah)  + bh;

        const float zg = 1.f / (1.f + expf(-(x0 + iz)));
        const float rg = 1.f / (1.f + expf(-(x1 + ir)));
        const float hh = tanhf(x2 + rg * ic);
        const float hp = hrow[col];
        const float hn = zg * hp + (1.f - zg) * hh;
        const float hsel = m ? hn : hp;     // masked steps carry state

        float* hdst = g_h + ((((size_t)((t + 1) & 1)) * 2 + dir) << 14);
        hdst[(b << 9) + col] = hsel;
        y[((size_t)b * T + tsrc) * 1024 + (dir << 9) + col] = m ? hn : 0.f;
        if (writeHidden && t == T - 1)
            hiddenOut[(b << 10) + (dir << 9) + col] = hsel;

        __threadfence();           // publish h writes before counter bump
        __syncthreads();
        if (tid == 0) atomicAdd(cnt, 1u);
    }
}

// ============================================================================
// Launch sequence (graph-capturable: kernel launches only)
// ============================================================================
extern "C" void kernel_launch(void* const* d_in, const int* in_sizes, int n_in,
                              void* d_out, int out_size) {
    (void)in_sizes; (void)n_in; (void)out_size;
    const float* inputs = (const float*)d_in[0];

    const float *k_[4][2], *r_[4][2], *bi_[4][2];
    for (int l = 0; l < 4; ++l)
        for (int d = 0; d < 2; ++d) {
            int base = 3 + l * 6 + d * 3;
            k_[l][d]  = (const float*)d_in[base + 0];
            r_[l][d]  = (const float*)d_in[base + 1];
            bi_[l][d] = (const float*)d_in[base + 2];
        }

    float *xzf, *xzb, *y0, *y1;
    unsigned char* mk;
    cudaGetSymbolAddress((void**)&xzf, g_xzf);
    cudaGetSymbolAddress((void**)&xzb, g_xzb);
    cudaGetSymbolAddress((void**)&y0, g_y0);
    cudaGetSymbolAddress((void**)&y1, g_y1);
    cudaGetSymbolAddress((void**)&mk, g_mask);

    cudaFuncSetAttribute(gru_rec_kernel,
                         cudaFuncAttributeMaxDynamicSharedMemorySize, REC_SMEM);

    float* outp = (float*)d_out;
    float* hid  = outp + (size_t)32 * 128 * 1024;

    const int   Ts[4] = {1024, 512, 256, 128};
    const int   Ks[4] = {240, 2048, 2048, 2048};
    const float* Asrc[4] = {inputs, y0, y1, y0};
    float*       Ydst[4] = {y0, y1, y0, outp};

    for (int l = 0; l < 4; ++l) {
        const int T = Ts[l], K = Ks[l];
        const int Tprev = l ? Ts[l - 1] : 0;
        const int mode  = l ? 1 : 0;
        const int rows  = 32 * T;

        if (l == 0)
            mask_in_kernel<<<(rows + 255) / 256, 256>>>(inputs, mk, rows);
        else
            mask_py_kernel<<<(rows + 255) / 256, 256>>>(Asrc[l], mk, T, Tprev);

        dim3 grid(12, rows / 128);
        gemm_xz_kernel<<<grid, 256>>>(Asrc[l], k_[l][0], bi_[l][0], xzf,
                                      K, T, Tprev, mode, 0);
        gemm_xz_kernel<<<grid, 256>>>(Asrc[l], k_[l][1], bi_[l][1], xzb,
                                      K, T, Tprev, mode, 1);

        zero_state_kernel<<<64, 256>>>();
        gru_rec_kernel<<<128, REC_THREADS, REC_SMEM>>>(
            xzf, xzb, r_[l][0], r_[l][1], bi_[l][0], bi_[l][1],
            mk, Ydst[l], T, (l == 3) ? 1 : 0, hid);
    }
}

// round 2
// speedup vs baseline: 1.1309x; 1.1309x over previous
#include <cuda_runtime.h>
#include <cuda_bf16.h>
#include <cstdint>

// ============================================================================
// Problem: 4-layer pyramidal BiGRU. B=32, H=512, 3H=1536.
// Layers: T = 1024,512,256,128 ; din = 240,2048,2048,2048
// ============================================================================

#define NB_PER_DIR 64
#define REC_THREADS 256

// ---------------- device scratch ----------------
__device__ float g_xzf[50331648];   // [32][1024][1536] max
__device__ float g_xzb[50331648];
__device__ float g_y0 [33554432];   // [32][1024][1024]
__device__ float g_y1 [16777216];   // [32][512][1024]
__device__ float g_h  [2 * 2 * 32 * 512];   // [parity][dir][B][H]
__device__ unsigned int g_flag[2 * 512];    // [dir][64 ctas], stride-8 padded
__device__ unsigned char g_mask[32 * 1024];

// ---------------- packed f32x2 helpers (recurrence) ----------------
__device__ __forceinline__ void fma2(unsigned long long& acc,
                                     unsigned long long a, unsigned long long b) {
    asm("fma.rn.f32x2 %0, %1, %2, %0;" : "+l"(acc) : "l"(a), "l"(b));
}
__device__ __forceinline__ float lo2(unsigned long long v) {
    return __uint_as_float((unsigned int)v);
}
__device__ __forceinline__ float hi2(unsigned long long v) {
    return __uint_as_float((unsigned int)(v >> 32));
}

// ---------------- bf16 split helpers (GEMM) ----------------
// pack two bf16 (rn) into one word: 'a' -> low half, 'b' -> high half
__device__ __forceinline__ unsigned int bfpack(float a, float b) {
    __nv_bfloat162 h = __floats2bfloat162_rn(a, b);
    return *reinterpret_cast<unsigned int*>(&h);
}
__device__ __forceinline__ float bfres(float x) {
    __nv_bfloat16 h = __float2bfloat16(x);
    return x - __bfloat162float(h);
}

#define MMA_BF16(c, a, b0, b1)                                              \
    asm volatile("mma.sync.aligned.m16n8k16.row.col.f32.bf16.bf16.f32 "     \
        "{%0,%1,%2,%3}, {%4,%5,%6,%7}, {%8,%9}, {%0,%1,%2,%3};"             \
        : "+f"((c)[0]), "+f"((c)[1]), "+f"((c)[2]), "+f"((c)[3])            \
        : "r"((a)[0]), "r"((a)[1]), "r"((a)[2]), "r"((a)[3]),               \
          "r"(b0), "r"(b1))

// ============================================================================
// Mask kernels (row masked iff ALL elements == 0, mirroring reference)
// ============================================================================
__global__ void mask_in_kernel(const float* __restrict__ x,
                               unsigned char* __restrict__ mk, int rows) {
    int r = blockIdx.x * blockDim.x + threadIdx.x;
    if (r >= rows) return;
    const float4* p = (const float4*)(x + (size_t)r * 240);
    bool any = false;
    for (int i = 0; i < 60; ++i) {
        float4 v = __ldg(p + i);
        any = any | (v.x != 0.f) | (v.y != 0.f) | (v.z != 0.f) | (v.w != 0.f);
        if (any) break;
    }
    mk[r] = any ? 1 : 0;
}

__global__ void mask_py_kernel(const float* __restrict__ y,
                               unsigned char* __restrict__ mk, int T, int Tprev) {
    int r = blockIdx.x * blockDim.x + threadIdx.x;
    int rows = 32 * T;
    if (r >= rows) return;
    int b = r / T, i = r - b * T;
    const float4* p = (const float4*)(y + (((size_t)b * Tprev + 2 * i) << 10));
    bool any = false;
    for (int q = 0; q < 512; ++q) {
        float4 v = __ldg(p + q);
        any = any | (v.x != 0.f) | (v.y != 0.f) | (v.z != 0.f) | (v.w != 0.f);
        if (any) break;
    }
    mk[r] = any ? 1 : 0;
}

__global__ void zero_state_kernel() {
    int i = blockIdx.x * blockDim.x + threadIdx.x;
    for (int k = i; k < 2 * 2 * 32 * 512; k += gridDim.x * blockDim.x)
        g_h[k] = 0.f;
    for (int k = i; k < 2 * 512; k += gridDim.x * blockDim.x)
        g_flag[k] = 0u;
}

// ============================================================================
// Input-projection GEMM via bf16x3 split on tensor cores (mma.sync m16n8k16).
//   C[m][n] = sum_k A(m,k) * W[k][n] + bias[n],  all shapes mult of tile.
//   Block 128x128, 256 threads = 8 warps (4 x 2), warp tile 32x64.
//   A gathered with pyramid/reverse addressing (row base is linear in k!).
// SMEM word layouts (custom, fragment-order, conflict-free):
//   a_sm[c2][m] : word packs A[m][2*c2], A[m][2*c2+1]   (c2 = 0..7, pad 140)
//   b_sm[k2][n] : word packs W[2*k2][n], W[2*k2+1][n]   (k2 = 0..7, pad 136)
// ============================================================================
#define PA 140
#define PB 136

__global__ void __launch_bounds__(256) gemm_xz_mma(
    const float* __restrict__ A, const float* __restrict__ W,
    const float* __restrict__ bias, float* __restrict__ C,
    int K, int Tcur, int Tprev, int mode, int rev) {
    __shared__ unsigned int a_hi[8 * PA], a_lo[8 * PA];
    __shared__ unsigned int b_hi[8 * PB], b_lo[8 * PB];

    const int tid  = threadIdx.x;
    const int lane = tid & 31, wid = tid >> 5;
    const int g = lane >> 2, t4 = lane & 3;
    const int warpM = wid & 3, warpN = wid >> 2;
    const int m0 = blockIdx.y << 7, n0 = blockIdx.x << 7;

    // ---- global load assignment ----
    const int ar  = tid >> 1;            // A row in tile 0..127
    const int ak  = (tid & 1) << 3;      // k offset 0 or 8
    const int bk2 = tid >> 5;            // W k-pair 0..7
    const int bn  = (tid & 31) << 2;     // W col 0..124

    // per-thread A row base (linear in k for both modes)
    const float* aRow;
    {
        int m  = m0 + ar;
        int bi = m / Tcur;
        int t  = m - bi * Tcur;
        int tt = rev ? (Tcur - 1 - t) : t;
        if (mode == 0) aRow = A + ((size_t)bi * Tcur + tt) * 240;
        else           aRow = A + (((size_t)bi * Tprev + 2 * tt) << 10);
    }

    float c_[2][8][4];
    #pragma unroll
    for (int mt = 0; mt < 2; ++mt)
        #pragma unroll
        for (int nt = 0; nt < 8; ++nt)
            #pragma unroll
            for (int i = 0; i < 4; ++i) c_[mt][nt][i] = 0.f;

    const int NT = K >> 4;

    float4 aA, aB, bA, bB;
    aA = *(const float4*)(aRow + ak);
    aB = *(const float4*)(aRow + ak + 4);
    {
        const float* pb = W + (size_t)(2 * bk2) * 1536 + n0 + bn;
        bA = *(const float4*)pb;
        bB = *(const float4*)(pb + 1536);
    }

    for (int kt = 0; kt < NT; ++kt) {
        // ---- convert + store to SMEM ----
        {
            int c2 = ak >> 1;
            a_hi[(c2 + 0) * PA + ar] = bfpack(aA.x, aA.y);
            a_hi[(c2 + 1) * PA + ar] = bfpack(aA.z, aA.w);
            a_hi[(c2 + 2) * PA + ar] = bfpack(aB.x, aB.y);
            a_hi[(c2 + 3) * PA + ar] = bfpack(aB.z, aB.w);
            a_lo[(c2 + 0) * PA + ar] = bfpack(bfres(aA.x), bfres(aA.y));
            a_lo[(c2 + 1) * PA + ar] = bfpack(bfres(aA.z), bfres(aA.w));
            a_lo[(c2 + 2) * PA + ar] = bfpack(bfres(aB.x), bfres(aB.y));
            a_lo[(c2 + 3) * PA + ar] = bfpack(bfres(aB.z), bfres(aB.w));

            int bidx = bk2 * PB + bn;
            uint2 h0 = {bfpack(bA.x, bB.x), bfpack(bA.y, bB.y)};
            uint2 h1 = {bfpack(bA.z, bB.z), bfpack(bA.w, bB.w)};
            uint2 l0 = {bfpack(bfres(bA.x), bfres(bB.x)),
                        bfpack(bfres(bA.y), bfres(bB.y))};
            uint2 l1 = {bfpack(bfres(bA.z), bfres(bB.z)),
                        bfpack(bfres(bA.w), bfres(bB.w))};
            *(uint2*)&b_hi[bidx]     = h0;
            *(uint2*)&b_hi[bidx + 2] = h1;
            *(uint2*)&b_lo[bidx]     = l0;
            *(uint2*)&b_lo[bidx + 2] = l1;
        }
        __syncthreads();

        // ---- prefetch next k16 ----
        if (kt + 1 < NT) {
            int k0 = (kt + 1) << 4;
            aA = *(const float4*)(aRow + k0 + ak);
            aB = *(const float4*)(aRow + k0 + ak + 4);
            const float* pb = W + ((size_t)k0 + 2 * bk2) * 1536 + n0 + bn;
            bA = *(const float4*)pb;
            bB = *(const float4*)(pb + 1536);
        }

        // ---- load A fragments ----
        unsigned int afh[2][4], afl[2][4];
        #pragma unroll
        for (int mt = 0; mt < 2; ++mt) {
            int r = warpM * 32 + mt * 16 + g;
            afh[mt][0] = a_hi[t4 * PA + r];
            afh[mt][1] = a_hi[t4 * PA + r + 8];
            afh[mt][2] = a_hi[(t4 + 4) * PA + r];
            afh[mt][3] = a_hi[(t4 + 4) * PA + r + 8];
            afl[mt][0] = a_lo[t4 * PA + r];
            afl[mt][1] = a_lo[t4 * PA + r + 8];
            afl[mt][2] = a_lo[(t4 + 4) * PA + r];
            afl[mt][3] = a_lo[(t4 + 4) * PA + r + 8];
        }

        // ---- mma over 8 n-tiles x 2 m-tiles x 3 splits ----
        #pragma unroll
        for (int nt = 0; nt < 8; ++nt) {
            int cc = warpN * 64 + nt * 8 + g;
            unsigned int bh0 = b_hi[t4 * PB + cc];
            unsigned int bh1 = b_hi[(t4 + 4) * PB + cc];
            unsigned int bl0 = b_lo[t4 * PB + cc];
            unsigned int bl1 = b_lo[(t4 + 4) * PB + cc];
            #pragma unroll
            for (int mt = 0; mt < 2; ++mt) {
                MMA_BF16(c_[mt][nt], afh[mt], bh0, bh1);   // hi*hi
                MMA_BF16(c_[mt][nt], afh[mt], bl0, bl1);   // hi*lo
                MMA_BF16(c_[mt][nt], afl[mt], bh0, bh1);   // lo*hi
            }
        }
        __syncthreads();
    }

    // ---- epilogue: bias + store ----
    #pragma unroll
    for (int nt = 0; nt < 8; ++nt) {
        int col = n0 + warpN * 64 + nt * 8 + t4 * 2;
        float bx = __ldg(bias + col);
        float by = __ldg(bias + col + 1);
        #pragma unroll
        for (int mt = 0; mt < 2; ++mt) {
            int r = m0 + warpM * 32 + mt * 16 + g;
            float2 o0 = {c_[mt][nt][0] + bx, c_[mt][nt][1] + by};
            float2 o1 = {c_[mt][nt][2] + bx, c_[mt][nt][3] + by};
            *(float2*)(C + (size_t)r * 1536 + col)       = o0;
            *(float2*)(C + (size_t)(r + 8) * 1536 + col) = o1;
        }
    }
}

// ============================================================================
// Recurrence: persistent flag-synced kernel (release/acquire flags, chunked
// double-overlapped h broadcast). 128 CTAs (64/dir), 1 CTA/SM, no deadlock.
// ============================================================================
#define REC_SMEM ((24 * 516 + 32 * 516) * 4)

__global__ void __launch_bounds__(REC_THREADS, 1) gru_rec_kernel(
    const float* __restrict__ xzf, const float* __restrict__ xzb,
    const float* __restrict__ rkf, const float* __restrict__ rkb,
    const float* __restrict__ bf,  const float* __restrict__ bb,
    const unsigned char* __restrict__ mask,
    float* __restrict__ y, int T, int writeHidden, float* __restrict__ hiddenOut) {
    extern __shared__ float sm[];
    float* sh_w = sm;               // [24][516]  (g*8+c)*516 + k
    float* sh_h = sm + 24 * 516;    // [32][516]

    const int tid = threadIdx.x;
    const int dir = blockIdx.x >> 6;
    const int j   = blockIdx.x & 63;
    const int cb  = j << 3;
    const int b   = tid >> 3;       // batch 0..31
    const int c8  = tid & 7;        // column-in-chunk 0..7
    const int col = cb + c8;

    const float* xz = dir ? xzb : xzf;
    const float* rk = dir ? rkb : rkf;
    const float* bi = (dir ? bb : bf) + 1536;   // b[1] row

    // one-time: stage weight slice into SMEM (column gather)
    for (int idx = tid; idx < 512 * 24; idx += REC_THREADS) {
        int k  = idx / 24;
        int gc = idx - k * 24;
        sh_w[gc * 516 + k] = __ldg(rk + (size_t)k * 1536 + (gc >> 3) * 512 + cb + (gc & 7));
    }
    const float bz = __ldg(bi + col);
    const float br = __ldg(bi + 512 + col);
    const float bh = __ldg(bi + 1024 + col);
    __syncthreads();

    const float* wz = sh_w + (0 * 8 + c8) * 516;
    const float* wr = sh_w + (1 * 8 + c8) * 516;
    const float* wh = sh_w + (2 * 8 + c8) * 516;
    const float* hrow = sh_h + b * 516;

    unsigned int* myflag = g_flag + dir * 512 + j * 8;
    const unsigned int* pollflag = g_flag + dir * 512 + (tid & 63) * 8;

    // staging assignment: 4 chunks of 128 k; thread stages 4 float4 per chunk
    const int sb  = (tid + 0 * 256) >> 5;   // will recompute per j below
    (void)sb;

    for (int t = 0; t < T; ++t) {
        // loads independent of h: xz + mask
        const int tsrc = dir ? (T - 1 - t) : t;
        const size_t xoff = ((size_t)b * T + t) * 1536;
        const float x0 = __ldg(xz + xoff + col);
        const float x1 = __ldg(xz + xoff + 512 + col);
        const float x2 = __ldg(xz + xoff + 1024 + col);
        const unsigned char m = mask[b * T + tsrc];

        // wait for all CTAs of this direction to publish step t-1
        if (t > 0) {
            if (tid < 64) {
                unsigned int v;
                do {
                    asm volatile("ld.acquire.gpu.global.u32 %0, [%1];"
                                 : "=r"(v) : "l"(pollflag) : "memory");
                } while ((int)v < t);
            }
            __syncthreads();
        }

        const float* hsrc = g_h + ((((size_t)(t & 1)) * 2 + dir) << 14);

        // prefetch chunk 0
        float4 hv[4];
        #pragma unroll
        for (int q = 0; q < 4; ++q) {
            int f = q * 256 + tid;              // float4 id within chunk
            int bb2 = f >> 5, kq = f & 31;
            hv[q] = __ldcg((const float4*)(hsrc + (bb2 << 9) + 0 * 128 + kq * 4));
        }

        unsigned long long az = 0ULL, ar2 = 0ULL, ah = 0ULL;

        #pragma unroll
        for (int c = 0; c < 4; ++c) {
            // stage chunk c
            #pragma unroll
            for (int q = 0; q < 4; ++q) {
                int f = q * 256 + tid;
                int bb2 = f >> 5, kq = f & 31;
                *(float4*)(sh_h + bb2 * 516 + c * 128 + kq * 4) = hv[q];
            }
            __syncthreads();
            // prefetch chunk c+1 (overlaps with compute below)
            if (c < 3) {
                #pragma unroll
                for (int q = 0; q < 4; ++q) {
                    int f = q * 256 + tid;
                    int bb2 = f >> 5, kq = f & 31;
                    hv[q] = __ldcg((const float4*)(hsrc + (bb2 << 9) + (c + 1) * 128 + kq * 4));
                }
            }
            // compute over this chunk's k range
            const int kbeg = c * 128;
            #pragma unroll 8
            for (int k = kbeg; k < kbeg + 128; k += 4) {
                ulonglong2 h2 = *(const ulonglong2*)(hrow + k);
                ulonglong2 z2 = *(const ulonglong2*)(wz + k);
                ulonglong2 r2 = *(const ulonglong2*)(wr + k);
                ulonglong2 c2 = *(const ulonglong2*)(wh + k);
                fma2(az,  h2.x, z2.x); fma2(az,  h2.y, z2.y);
                fma2(ar2, h2.x, r2.x); fma2(ar2, h2.y, r2.y);
                fma2(ah,  h2.x, c2.x); fma2(ah,  h2.y, c2.y);
            }
        }

        const float iz = lo2(az)  + hi2(az)  + bz;
        const float ir = lo2(ar2) + hi2(ar2) + br;
        const float ic = lo2(ah)  + hi2(ah)  + bh;

        const float zg = 1.f / (1.f + expf(-(x0 + iz)));
        const float rg = 1.f / (1.f + expf(-(x1 + ir)));
        const float hh = tanhf(x2 + rg * ic);
        const float hp = hrow[col];
        const float hn = zg * hp + (1.f - zg) * hh;
        const float hsel = m ? hn : hp;

        float* hdst = g_h + ((((size_t)((t + 1) & 1)) * 2 + dir) << 14);
        hdst[(b << 9) + col] = hsel;
        y[((size_t)b * T + tsrc) * 1024 + (dir << 9) + col] = m ? hn : 0.f;
        if (writeHidden && t == T - 1)
            hiddenOut[(b << 10) + (dir << 9) + col] = hsel;

        __syncthreads();   // all h stores issued
        if (tid == 0) {
            unsigned int v = (unsigned int)(t + 1);
            asm volatile("st.release.gpu.global.u32 [%0], %1;"
                         :: "l"(myflag), "r"(v) : "memory");
        }
    }
}

// ============================================================================
// Launch sequence (graph-capturable)
// ============================================================================
extern "C" void kernel_launch(void* const* d_in, const int* in_sizes, int n_in,
                              void* d_out, int out_size) {
    (void)in_sizes; (void)n_in; (void)out_size;
    const float* inputs = (const float*)d_in[0];

    const float *k_[4][2], *r_[4][2], *bi_[4][2];
    for (int l = 0; l < 4; ++l)
        for (int d = 0; d < 2; ++d) {
            int base = 3 + l * 6 + d * 3;
            k_[l][d]  = (const float*)d_in[base + 0];
            r_[l][d]  = (const float*)d_in[base + 1];
            bi_[l][d] = (const float*)d_in[base + 2];
        }

    float *xzf, *xzb, *y0, *y1;
    unsigned char* mk;
    cudaGetSymbolAddress((void**)&xzf, g_xzf);
    cudaGetSymbolAddress((void**)&xzb, g_xzb);
    cudaGetSymbolAddress((void**)&y0, g_y0);
    cudaGetSymbolAddress((void**)&y1, g_y1);
    cudaGetSymbolAddress((void**)&mk, g_mask);

    cudaFuncSetAttribute(gru_rec_kernel,
                         cudaFuncAttributeMaxDynamicSharedMemorySize, REC_SMEM);

    float* outp = (float*)d_out;
    float* hid  = outp + (size_t)32 * 128 * 1024;

    const int   Ts[4] = {1024, 512, 256, 128};
    const int   Ks[4] = {240, 2048, 2048, 2048};
    const float* Asrc[4] = {inputs, y0, y1, y0};
    float*       Ydst[4] = {y0, y1, y0, outp};

    for (int l = 0; l < 4; ++l) {
        const int T = Ts[l], K = Ks[l];
        const int Tprev = l ? Ts[l - 1] : 0;
        const int mode  = l ? 1 : 0;
        const int rows  = 32 * T;

        if (l == 0)
            mask_in_kernel<<<(rows + 255) / 256, 256>>>(inputs, mk, rows);
        else
            mask_py_kernel<<<(rows + 255) / 256, 256>>>(Asrc[l], mk, T, Tprev);

        dim3 grid(12, rows / 128);
        gemm_xz_mma<<<grid, 256>>>(Asrc[l], k_[l][0], bi_[l][0], xzf,
                                   K, T, Tprev, mode, 0);
        gemm_xz_mma<<<grid, 256>>>(Asrc[l], k_[l][1], bi_[l][1], xzb,
                                   K, T, Tprev, mode, 1);

        zero_state_kernel<<<64, 256>>>();
        gru_rec_kernel<<<128, REC_THREADS, REC_SMEM>>>(
            xzf, xzb, r_[l][0], r_[l][1], bi_[l][0], bi_[l][1],
            mk, Ydst[l], T, (l == 3) ? 1 : 0, hid);
    }
}

// round 3
// speedup vs baseline: 1.2049x; 1.0654x over previous
#include <cuda_runtime.h>
#include <cuda_bf16.h>
#include <cstdint>

// ============================================================================
// 4-layer pyramidal BiGRU. B=32, H=512, 3H=1536.
// Layers l=0..3: T = 1024,512,256,128 ; din = 240,2048,2048,2048
// ============================================================================

#define REC_THREADS 256

// ---------------- static device scratch ----------------
__device__ float g_xzf[50331648];                 // [32][1024][1536] max
__device__ float g_xzb[50331648];
__device__ float g_h[2 * 2 * 32 * 512];           // [parity][dir][B][H]
__device__ unsigned int g_flag[2 * 512];          // [dir][64 ctas] stride-8
__device__ unsigned char g_mask[65536];           // per-layer offsets
__device__ __nv_bfloat16 g_whi[19611648], g_wlo[19611648];
__device__ __nv_bfloat16 g_inhi[7864320],  g_inlo[7864320];
__device__ __nv_bfloat16 g_yh0[33554432],  g_yl0[33554432];
__device__ __nv_bfloat16 g_yh1[16777216],  g_yl1[16777216];

// ---------------- packed f32x2 helpers (recurrence) ----------------
__device__ __forceinline__ void fma2(unsigned long long& acc,
                                     unsigned long long a, unsigned long long b) {
    asm("fma.rn.f32x2 %0, %1, %2, %0;" : "+l"(acc) : "l"(a), "l"(b));
}
__device__ __forceinline__ float lo2(unsigned long long v) {
    return __uint_as_float((unsigned int)v);
}
__device__ __forceinline__ float hi2(unsigned long long v) {
    return __uint_as_float((unsigned int)(v >> 32));
}

// ---------------- mma / ldmatrix ----------------
#define MMA_BF16(c, a, b0, b1)                                              \
    asm volatile("mma.sync.aligned.m16n8k16.row.col.f32.bf16.bf16.f32 "     \
        "{%0,%1,%2,%3}, {%4,%5,%6,%7}, {%8,%9}, {%0,%1,%2,%3};"             \
        : "+f"((c)[0]), "+f"((c)[1]), "+f"((c)[2]), "+f"((c)[3])            \
        : "r"((a)[0]), "r"((a)[1]), "r"((a)[2]), "r"((a)[3]),               \
          "r"(b0), "r"(b1))

#define LDSM4(R, addr)                                                      \
    asm volatile("ldmatrix.sync.aligned.m8n8.x4.shared.b16 "                \
        "{%0,%1,%2,%3}, [%4];"                                              \
        : "=r"((R)[0]), "=r"((R)[1]), "=r"((R)[2]), "=r"((R)[3])            \
        : "r"(addr))

#define LDSM2T(r0, r1, addr)                                                \
    asm volatile("ldmatrix.sync.aligned.m8n8.x2.trans.shared.b16 "          \
        "{%0,%1}, [%2];" : "=r"(r0), "=r"(r1) : "r"(addr))

__device__ __forceinline__ unsigned int smaddr(const void* p) {
    return (unsigned int)__cvta_generic_to_shared(p);
}

// ============================================================================
// prep kernel: convert 8 weight matrices + layer-0 input to bf16 hi/lo,
// compute layer-0 mask, zero flags. One launch, grid-stride everything.
// ============================================================================
__device__ __forceinline__ void cvt4(float4 v, uint2& hi, uint2& lo) {
    __nv_bfloat162 h0 = __floats2bfloat162_rn(v.x, v.y);
    __nv_bfloat162 h1 = __floats2bfloat162_rn(v.z, v.w);
    float2 f0 = __bfloat1622float2(h0);
    float2 f1 = __bfloat1622float2(h1);
    __nv_bfloat162 l0 = __floats2bfloat162_rn(v.x - f0.x, v.y - f0.y);
    __nv_bfloat162 l1 = __floats2bfloat162_rn(v.z - f1.x, v.w - f1.y);
    hi.x = *(unsigned int*)&h0; hi.y = *(unsigned int*)&h1;
    lo.x = *(unsigned int*)&l0; lo.y = *(unsigned int*)&l1;
}

#define WSZ0 368640
#define WSZ1 3145728

__global__ void prep_kernel(const float* __restrict__ in,
                            const float* w0, const float* w1, const float* w2,
                            const float* w3, const float* w4, const float* w5,
                            const float* w6, const float* w7) {
    const float* ws[8] = {w0, w1, w2, w3, w4, w5, w6, w7};
    const int sz[8]  = {WSZ0, WSZ0, WSZ1, WSZ1, WSZ1, WSZ1, WSZ1, WSZ1};
    const int off[8] = {0, WSZ0, 2 * WSZ0, 2 * WSZ0 + WSZ1, 2 * WSZ0 + 2 * WSZ1,
                        2 * WSZ0 + 3 * WSZ1, 2 * WSZ0 + 4 * WSZ1, 2 * WSZ0 + 5 * WSZ1};
    const int gid = blockIdx.x * blockDim.x + threadIdx.x;
    const int stride = gridDim.x * blockDim.x;

    #pragma unroll 1
    for (int w = 0; w < 8; ++w) {
        const float4* W = (const float4*)ws[w];
        uint2* hi = (uint2*)(g_whi + off[w]);
        uint2* lo = (uint2*)(g_wlo + off[w]);
        int n4 = sz[w] >> 2;
        for (int i = gid; i < n4; i += stride) {
            uint2 h, l; cvt4(__ldg(W + i), h, l);
            hi[i] = h; lo[i] = l;
        }
    }
    {
        const float4* X = (const float4*)in;
        uint2* hi = (uint2*)g_inhi; uint2* lo = (uint2*)g_inlo;
        for (int i = gid; i < (7864320 >> 2); i += stride) {
            uint2 h, l; cvt4(__ldg(X + i), h, l);
            hi[i] = h; lo[i] = l;
        }
    }
    // layer-0 mask
    for (int r = gid; r < 32768; r += stride) {
        const float4* p = (const float4*)(in + (size_t)r * 240);
        bool any = false;
        for (int i = 0; i < 60; ++i) {
            float4 v = __ldg(p + i);
            any = any | (v.x != 0.f) | (v.y != 0.f) | (v.z != 0.f) | (v.w != 0.f);
            if (any) break;
        }
        g_mask[r] = any ? 1 : 0;
    }
    for (int i = gid; i < 2 * 512; i += stride) g_flag[i] = 0u;
}

// derive pyramid mask: next[b,i] = cur[b,2i] | cur[b,2i+1]
__global__ void mask_derive(const unsigned char* __restrict__ src,
                            unsigned char* __restrict__ dst, int T) {
    int r = blockIdx.x * blockDim.x + threadIdx.x;
    if (r >= 32 * T) return;
    int b = r / T, i = r - b * T;
    dst[r] = (unsigned char)(src[b * 2 * T + 2 * i] | src[b * 2 * T + 2 * i + 1]);
}

// ============================================================================
// Input-projection GEMM, all-bf16 operands (pre-split hi/lo), ldmatrix + mma.
//   C[m][n] = sum_k A(m,k)*W[k][n] + bias[n]; 128x128x16 tile, 8 warps.
//   3-term split: hi*hi + hi*lo + lo*hi.
// ============================================================================
__global__ void __launch_bounds__(256) gemm_xz(
    const __nv_bfloat16* __restrict__ Ahi, const __nv_bfloat16* __restrict__ Alo,
    const __nv_bfloat16* __restrict__ Whi, const __nv_bfloat16* __restrict__ Wlo,
    const float* __restrict__ bias, float* __restrict__ C,
    int K, int lda, int Tcur, int rev) {
    __shared__ __align__(16) __nv_bfloat16 a_hi[128 * 24], a_lo[128 * 24];
    __shared__ __align__(16) __nv_bfloat16 w_hi[16 * 152], w_lo[16 * 152];

    const int tid  = threadIdx.x;
    const int lane = tid & 31, wid = tid >> 5;
    const int g = lane >> 2, t4 = lane & 3;
    const int warpM = wid & 3, warpN = wid >> 2;
    const int m0 = blockIdx.y << 7, n0 = blockIdx.x << 7;

    // fill assignments
    const int ar = tid >> 1;           // A row 0..127
    const int ak = (tid & 1) << 3;     // k offset 0/8
    const int wk = tid >> 4;           // W k row 0..15
    const int wc = (tid & 15) << 3;    // W col 0..120

    // A row base
    const __nv_bfloat16 *pAh, *pAl;
    {
        int m  = m0 + ar;
        int bi = m / Tcur;
        int t  = m - bi * Tcur;
        int tt = rev ? (Tcur - 1 - t) : t;
        size_t base = ((size_t)bi * Tcur + tt) * lda + ak;
        pAh = Ahi + base; pAl = Alo + base;
    }
    const __nv_bfloat16* pWh = Whi + (size_t)wk * 1536 + n0 + wc;
    const __nv_bfloat16* pWl = Wlo + (size_t)wk * 1536 + n0 + wc;

    // ldmatrix lane addresses (bytes)
    const int aRowL = warpM * 32 + (lane & 15);
    const int aKofL = (lane & 16) >> 1;             // 0 or 8
    const unsigned int aHiAddr = smaddr(a_hi) + (unsigned)((aRowL * 24 + aKofL) * 2);
    const unsigned int aLoAddr = smaddr(a_lo) + (unsigned)((aRowL * 24 + aKofL) * 2);
    const unsigned int bHiAddr = smaddr(w_hi) + (unsigned)(((lane & 15) * 152 + warpN * 64) * 2);
    const unsigned int bLoAddr = smaddr(w_lo) + (unsigned)(((lane & 15) * 152 + warpN * 64) * 2);

    float c_[2][8][4];
    #pragma unroll
    for (int mt = 0; mt < 2; ++mt)
        #pragma unroll
        for (int nt = 0; nt < 8; ++nt)
            #pragma unroll
            for (int i = 0; i < 4; ++i) c_[mt][nt][i] = 0.f;

    const int NT = K >> 4;
    uint4 rAh = *(const uint4*)pAh;
    uint4 rAl = *(const uint4*)pAl;
    uint4 rWh = *(const uint4*)pWh;
    uint4 rWl = *(const uint4*)pWl;

    for (int kt = 0; kt < NT; ++kt) {
        *(uint4*)(a_hi + ar * 24 + ak) = rAh;
        *(uint4*)(a_lo + ar * 24 + ak) = rAl;
        *(uint4*)(w_hi + wk * 152 + wc) = rWh;
        *(uint4*)(w_lo + wk * 152 + wc) = rWl;
        __syncthreads();

        if (kt + 1 < NT) {
            int k0 = (kt + 1) << 4;
            rAh = *(const uint4*)(pAh + k0);
            rAl = *(const uint4*)(pAl + k0);
            rWh = *(const uint4*)(pWh + (size_t)k0 * 1536);
            rWl = *(const uint4*)(pWl + (size_t)k0 * 1536);
        }

        unsigned int afh[2][4], afl[2][4];
        #pragma unroll
        for (int mt = 0; mt < 2; ++mt) {
            LDSM4(afh[mt], aHiAddr + mt * 768);
            LDSM4(afl[mt], aLoAddr + mt * 768);
        }

        #pragma unroll
        for (int nt = 0; nt < 8; ++nt) {
            unsigned int bh0, bh1, bl0, bl1;
            LDSM2T(bh0, bh1, bHiAddr + nt * 16);
            LDSM2T(bl0, bl1, bLoAddr + nt * 16);
            #pragma unroll
            for (int mt = 0; mt < 2; ++mt) {
                MMA_BF16(c_[mt][nt], afh[mt], bh0, bh1);
                MMA_BF16(c_[mt][nt], afh[mt], bl0, bl1);
                MMA_BF16(c_[mt][nt], afl[mt], bh0, bh1);
            }
        }
        __syncthreads();
    }

    // epilogue: bias + store
    #pragma unroll
    for (int nt = 0; nt < 8; ++nt) {
        int col = n0 + warpN * 64 + nt * 8 + t4 * 2;
        float bx = __ldg(bias + col);
        float by = __ldg(bias + col + 1);
        #pragma unroll
        for (int mt = 0; mt < 2; ++mt) {
            int r = m0 + warpM * 32 + mt * 16 + g;
            float2 o0 = {c_[mt][nt][0] + bx, c_[mt][nt][1] + by};
            float2 o1 = {c_[mt][nt][2] + bx, c_[mt][nt][3] + by};
            *(float2*)(C + (size_t)r * 1536 + col)       = o0;
            *(float2*)(C + (size_t)(r + 8) * 1536 + col) = o1;
        }
    }
}

// ============================================================================
// Recurrence: persistent flag-synced kernel. 128 CTAs (64/dir), 1 CTA/SM.
// Flag epochs across layers (no zeroing between layers); t==0 uses h==0.
// Emits y as bf16 hi/lo (for next layer's GEMM) and/or f32 (final layer).
// ============================================================================
#define REC_SMEM ((24 * 516 + 32 * 516) * 4)

__global__ void __launch_bounds__(REC_THREADS, 1) gru_rec_kernel(
    const float* __restrict__ xzf, const float* __restrict__ xzb,
    const float* __restrict__ rkf, const float* __restrict__ rkb,
    const float* __restrict__ bf,  const float* __restrict__ bb,
    const unsigned char* __restrict__ mask,
    float* __restrict__ y32,
    __nv_bfloat16* __restrict__ yhi, __nv_bfloat16* __restrict__ ylo,
    int T, int flagBase, int writeHidden, float* __restrict__ hiddenOut) {
    extern __shared__ float sm[];
    float* sh_w = sm;               // [24][516]
    float* sh_h = sm + 24 * 516;    // [32][516]

    const int tid = threadIdx.x;
    const int dir = blockIdx.x >> 6;
    const int j   = blockIdx.x & 63;
    const int cb  = j << 3;
    const int b   = tid >> 3;       // batch 0..31
    const int c8  = tid & 7;
    const int col = cb + c8;

    const float* xz = dir ? xzb : xzf;
    const float* rk = dir ? rkb : rkf;
    const float* bi = (dir ? bb : bf) + 1536;   // b[1]

    for (int idx = tid; idx < 512 * 24; idx += REC_THREADS) {
        int k  = idx / 24;
        int gc = idx - k * 24;
        sh_w[gc * 516 + k] = __ldg(rk + (size_t)k * 1536 + (gc >> 3) * 512 + cb + (gc & 7));
    }
    const float bz = __ldg(bi + col);
    const float br = __ldg(bi + 512 + col);
    const float bh = __ldg(bi + 1024 + col);
    __syncthreads();

    const float* wz = sh_w + (0 * 8 + c8) * 516;
    const float* wr = sh_w + (1 * 8 + c8) * 516;
    const float* wh = sh_w + (2 * 8 + c8) * 516;
    const float* hrow = sh_h + b * 516;

    unsigned int* myflag = g_flag + dir * 512 + j * 8;
    const unsigned int* pollflag = g_flag + dir * 512 + (tid & 63) * 8;

    for (int t = 0; t < T; ++t) {
        const int tsrc = dir ? (T - 1 - t) : t;
        const size_t xoff = ((size_t)b * T + t) * 1536;
        const float x0 = __ldg(xz + xoff + col);
        const float x1 = __ldg(xz + xoff + 512 + col);
        const float x2 = __ldg(xz + xoff + 1024 + col);
        const unsigned char m = mask[b * T + tsrc];

        unsigned long long az = 0ULL, ar2 = 0ULL, ah = 0ULL;
        float hp = 0.f;

        if (t > 0) {
            if (tid < 64) {
                unsigned int v;
                unsigned int target = (unsigned int)(flagBase + t);
                do {
                    asm volatile("ld.acquire.gpu.global.u32 %0, [%1];"
                                 : "=r"(v) : "l"(pollflag) : "memory");
                } while (v < target);
            }
            __syncthreads();

            const float* hsrc = g_h + ((((size_t)(t & 1)) * 2 + dir) << 14);

            float4 hv[4];
            #pragma unroll
            for (int q = 0; q < 4; ++q) {
                int f = q * 256 + tid;
                int bb2 = f >> 5, kq = f & 31;
                hv[q] = __ldcg((const float4*)(hsrc + (bb2 << 9) + kq * 4));
            }

            #pragma unroll
            for (int c = 0; c < 4; ++c) {
                #pragma unroll
                for (int q = 0; q < 4; ++q) {
                    int f = q * 256 + tid;
                    int bb2 = f >> 5, kq = f & 31;
                    *(float4*)(sh_h + bb2 * 516 + c * 128 + kq * 4) = hv[q];
                }
                __syncthreads();
                if (c < 3) {
                    #pragma unroll
                    for (int q = 0; q < 4; ++q) {
                        int f = q * 256 + tid;
                        int bb2 = f >> 5, kq = f & 31;
                        hv[q] = __ldcg((const float4*)(hsrc + (bb2 << 9) + (c + 1) * 128 + kq * 4));
                    }
                }
                const int kbeg = c * 128;
                #pragma unroll 8
                for (int k = kbeg; k < kbeg + 128; k += 4) {
                    ulonglong2 h2 = *(const ulonglong2*)(hrow + k);
                    ulonglong2 z2 = *(const ulonglong2*)(wz + k);
                    ulonglong2 r2 = *(const ulonglong2*)(wr + k);
                    ulonglong2 c2 = *(const ulonglong2*)(wh + k);
                    fma2(az,  h2.x, z2.x); fma2(az,  h2.y, z2.y);
                    fma2(ar2, h2.x, r2.x); fma2(ar2, h2.y, r2.y);
                    fma2(ah,  h2.x, c2.x); fma2(ah,  h2.y, c2.y);
                }
            }
            hp = hrow[col];
        }

        const float iz = lo2(az)  + hi2(az)  + bz;
        const float ir = lo2(ar2) + hi2(ar2) + br;
        const float ic = lo2(ah)  + hi2(ah)  + bh;

        const float zg = 1.f / (1.f + expf(-(x0 + iz)));
        const float rg = 1.f / (1.f + expf(-(x1 + ir)));
        const float hh = tanhf(x2 + rg * ic);
        const float hn = zg * hp + (1.f - zg) * hh;
        const float hsel = m ? hn : hp;
        const float yval = m ? hn : 0.f;

        float* hdst = g_h + ((((size_t)((t + 1) & 1)) * 2 + dir) << 14);
        hdst[(b << 9) + col] = hsel;

        const size_t yidx = ((size_t)b * T + tsrc) * 1024 + (dir << 9) + col;
        if (yhi) {
            __nv_bfloat16 h16 = __float2bfloat16(yval);
            yhi[yidx] = h16;
            ylo[yidx] = __float2bfloat16(yval - __bfloat162float(h16));
        }
        if (y32) y32[yidx] = yval;
        if (writeHidden && t == T - 1)
            hiddenOut[(b << 10) + (dir << 9) + col] = hsel;

        __syncthreads();
        if (tid == 0) {
            unsigned int v = (unsigned int)(flagBase + t + 1);
            asm volatile("st.release.gpu.global.u32 [%0], %1;"
                         :: "l"(myflag), "r"(v) : "memory");
        }
    }
}

// ============================================================================
// Launch sequence (graph-capturable)
// ============================================================================
extern "C" void kernel_launch(void* const* d_in, const int* in_sizes, int n_in,
                              void* d_out, int out_size) {
    (void)in_sizes; (void)n_in; (void)out_size;
    const float* inputs = (const float*)d_in[0];

    const float *k_[4][2], *r_[4][2], *bi_[4][2];
    for (int l = 0; l < 4; ++l)
        for (int d = 0; d < 2; ++d) {
            int base = 3 + l * 6 + d * 3;
            k_[l][d]  = (const float*)d_in[base + 0];
            r_[l][d]  = (const float*)d_in[base + 1];
            bi_[l][d] = (const float*)d_in[base + 2];
        }

    float *xzf, *xzb;
    unsigned char* mk;
    __nv_bfloat16 *whi, *wlo, *inhi, *inlo, *yh0, *yl0, *yh1, *yl1;
    cudaGetSymbolAddress((void**)&xzf, g_xzf);
    cudaGetSymbolAddress((void**)&xzb, g_xzb);
    cudaGetSymbolAddress((void**)&mk, g_mask);
    cudaGetSymbolAddress((void**)&whi, g_whi);
    cudaGetSymbolAddress((void**)&wlo, g_wlo);
    cudaGetSymbolAddress((void**)&inhi, g_inhi);
    cudaGetSymbolAddress((void**)&inlo, g_inlo);
    cudaGetSymbolAddress((void**)&yh0, g_yh0);
    cudaGetSymbolAddress((void**)&yl0, g_yl0);
    cudaGetSymbolAddress((void**)&yh1, g_yh1);
    cudaGetSymbolAddress((void**)&yl1, g_yl1);

    cudaFuncSetAttribute(gru_rec_kernel,
                         cudaFuncAttributeMaxDynamicSharedMemorySize, REC_SMEM);

    float* outp = (float*)d_out;
    float* hid  = outp + (size_t)32 * 128 * 1024;

    // prep: all weight/input bf16 conversion + layer-0 mask + flag reset
    prep_kernel<<<2048, 256>>>(inputs, k_[0][0], k_[0][1], k_[1][0], k_[1][1],
                               k_[2][0], k_[2][1], k_[3][0], k_[3][1]);

    const int Ts[4]   = {1024, 512, 256, 128};
    const int Ks[4]   = {240, 2048, 2048, 2048};
    const int ldas[4] = {240, 2048, 2048, 2048};
    const int woff[4][2] = {{0, WSZ0},
                            {2 * WSZ0, 2 * WSZ0 + WSZ1},
                            {2 * WSZ0 + 2 * WSZ1, 2 * WSZ0 + 3 * WSZ1},
                            {2 * WSZ0 + 4 * WSZ1, 2 * WSZ0 + 5 * WSZ1}};
    const int moff[4] = {0, 32768, 49152, 57344};
    const int fbase[4] = {0, 1024, 1536, 1792};

    const __nv_bfloat16* Ah[4] = {inhi, yh0, yh1, yh0};
    const __nv_bfloat16* Al[4] = {inlo, yl0, yl1, yl0};
    __nv_bfloat16* Yh[4] = {yh0, yh1, yh0, nullptr};
    __nv_bfloat16* Yl[4] = {yl0, yl1, yl0, nullptr};
    float* Y32[4] = {nullptr, nullptr, nullptr, outp};

    for (int l = 0; l < 4; ++l) {
        const int T = Ts[l], K = Ks[l];
        const int rows = 32 * T;

        if (l > 0)
            mask_derive<<<(rows + 255) / 256, 256>>>(mk + moff[l - 1],
                                                     mk + moff[l], T);

        dim3 grid(12, rows / 128);
        gemm_xz<<<grid, 256>>>(Ah[l], Al[l], whi + woff[l][0], wlo + woff[l][0],
                               bi_[l][0], xzf, K, ldas[l], T, 0);
        gemm_xz<<<grid, 256>>>(Ah[l], Al[l], whi + woff[l][1], wlo + woff[l][1],
                               bi_[l][1], xzb, K, ldas[l], T, 1);

        gru_rec_kernel<<<128, REC_THREADS, REC_SMEM>>>(
            xzf, xzb, r_[l][0], r_[l][1], bi_[l][0], bi_[l][1],
            mk + moff[l], Y32[l], Yh[l], Yl[l], T, fbase[l],
            (l == 3) ? 1 : 0, hid);
    }
}

// round 5
// speedup vs baseline: 1.2814x; 1.0635x over previous
#include <cuda_runtime.h>
#include <cuda_bf16.h>
#include <cstdint>

// ============================================================================
// 4-layer pyramidal BiGRU. B=32, H=512, 3H=1536.
// Layers l=0..3: T = 1024,512,256,128 ; din = 240,2048,2048,2048
// ============================================================================

#define REC_THREADS 256

// ---------------- static device scratch ----------------
__device__ float g_xzf[50331648];                 // [32][1024][1536] max
__device__ float g_xzb[50331648];
__device__ float g_h[2 * 2 * 32 * 512];           // [parity][dir][B][H]
__device__ unsigned int g_flag[2 * 512];          // [dir][64 ctas] stride-8
__device__ unsigned char g_mask[65536];           // per-layer offsets
__device__ __nv_bfloat16 g_whi[19611648], g_wlo[19611648];
__device__ __nv_bfloat16 g_inhi[7864320],  g_inlo[7864320];
__device__ __nv_bfloat16 g_yh0[33554432],  g_yl0[33554432];
__device__ __nv_bfloat16 g_yh1[16777216],  g_yl1[16777216];

// ---------------- packed f32x2 helpers (recurrence) ----------------
__device__ __forceinline__ void fma2(unsigned long long& acc,
                                     unsigned long long a, unsigned long long b) {
    asm("fma.rn.f32x2 %0, %1, %2, %0;" : "+l"(acc) : "l"(a), "l"(b));
}
__device__ __forceinline__ float lo2(unsigned long long v) {
    return __uint_as_float((unsigned int)v);
}
__device__ __forceinline__ float hi2(unsigned long long v) {
    return __uint_as_float((unsigned int)(v >> 32));
}

// ---------------- mma / ldmatrix ----------------
#define MMA_BF16(c, a, b0, b1)                                              \
    asm volatile("mma.sync.aligned.m16n8k16.row.col.f32.bf16.bf16.f32 "     \
        "{%0,%1,%2,%3}, {%4,%5,%6,%7}, {%8,%9}, {%0,%1,%2,%3};"             \
        : "+f"((c)[0]), "+f"((c)[1]), "+f"((c)[2]), "+f"((c)[3])            \
        : "r"((a)[0]), "r"((a)[1]), "r"((a)[2]), "r"((a)[3]),               \
          "r"(b0), "r"(b1))

#define LDSM4(R, addr)                                                      \
    asm volatile("ldmatrix.sync.aligned.m8n8.x4.shared.b16 "                \
        "{%0,%1,%2,%3}, [%4];"                                              \
        : "=r"((R)[0]), "=r"((R)[1]), "=r"((R)[2]), "=r"((R)[3])            \
        : "r"(addr))

#define LDSM4T(R, addr)                                                     \
    asm volatile("ldmatrix.sync.aligned.m8n8.x4.trans.shared.b16 "          \
        "{%0,%1,%2,%3}, [%4];"                                              \
        : "=r"((R)[0]), "=r"((R)[1]), "=r"((R)[2]), "=r"((R)[3])            \
        : "r"(addr))

__device__ __forceinline__ unsigned int smaddr(const void* p) {
    return (unsigned int)__cvta_generic_to_shared(p);
}

// ============================================================================
// prep kernel: convert 8 weight matrices + layer-0 input to bf16 hi/lo,
// compute layer-0 mask, zero flags.
// ============================================================================
__device__ __forceinline__ void cvt4(float4 v, uint2& hi, uint2& lo) {
    __nv_bfloat162 h0 = __floats2bfloat162_rn(v.x, v.y);
    __nv_bfloat162 h1 = __floats2bfloat162_rn(v.z, v.w);
    float2 f0 = __bfloat1622float2(h0);
    float2 f1 = __bfloat1622float2(h1);
    __nv_bfloat162 l0 = __floats2bfloat162_rn(v.x - f0.x, v.y - f0.y);
    __nv_bfloat162 l1 = __floats2bfloat162_rn(v.z - f1.x, v.w - f1.y);
    hi.x = *(unsigned int*)&h0; hi.y = *(unsigned int*)&h1;
    lo.x = *(unsigned int*)&l0; lo.y = *(unsigned int*)&l1;
}

#define WSZ0 368640
#define WSZ1 3145728

__global__ void prep_kernel(const float* __restrict__ in,
                            const float* w0, const float* w1, const float* w2,
                            const float* w3, const float* w4, const float* w5,
                            const float* w6, const float* w7) {
    const float* ws[8] = {w0, w1, w2, w3, w4, w5, w6, w7};
    const int sz[8]  = {WSZ0, WSZ0, WSZ1, WSZ1, WSZ1, WSZ1, WSZ1, WSZ1};
    const int off[8] = {0, WSZ0, 2 * WSZ0, 2 * WSZ0 + WSZ1, 2 * WSZ0 + 2 * WSZ1,
                        2 * WSZ0 + 3 * WSZ1, 2 * WSZ0 + 4 * WSZ1, 2 * WSZ0 + 5 * WSZ1};
    const int gid = blockIdx.x * blockDim.x + threadIdx.x;
    const int stride = gridDim.x * blockDim.x;

    #pragma unroll 1
    for (int w = 0; w < 8; ++w) {
        const float4* W = (const float4*)ws[w];
        uint2* hi = (uint2*)(g_whi + off[w]);
        uint2* lo = (uint2*)(g_wlo + off[w]);
        int n4 = sz[w] >> 2;
        for (int i = gid; i < n4; i += stride) {
            uint2 h, l; cvt4(__ldg(W + i), h, l);
            hi[i] = h; lo[i] = l;
        }
    }
    {
        const float4* X = (const float4*)in;
        uint2* hi = (uint2*)g_inhi; uint2* lo = (uint2*)g_inlo;
        for (int i = gid; i < (7864320 >> 2); i += stride) {
            uint2 h, l; cvt4(__ldg(X + i), h, l);
            hi[i] = h; lo[i] = l;
        }
    }
    // layer-0 mask
    for (int r = gid; r < 32768; r += stride) {
        const float4* p = (const float4*)(in + (size_t)r * 240);
        bool any = false;
        for (int i = 0; i < 60; ++i) {
            float4 v = __ldg(p + i);
            any = any | (v.x != 0.f) | (v.y != 0.f) | (v.z != 0.f) | (v.w != 0.f);
            if (any) break;
        }
        g_mask[r] = any ? 1 : 0;
    }
    for (int i = gid; i < 2 * 512; i += stride) g_flag[i] = 0u;
}

// ============================================================================
// Input-projection GEMM, bf16 hi/lo, mma.sync m16n8k16, tile 128x256x16.
// grid = (6, rows/128, 2): z = direction (0 fwd, 1 bwd=time-reversed A rows).
// 8 warps: warpM 0..3 (32 rows), warpN 0..1 (128 cols) -> 2x16 mma tiles.
// Fully-masked tiles (batch tail beyond length) are skipped entirely.
// ============================================================================
__global__ void __launch_bounds__(256, 1) gemm_xz(
    const __nv_bfloat16* __restrict__ Ahi, const __nv_bfloat16* __restrict__ Alo,
    int lda,
    const __nv_bfloat16* __restrict__ WhiF, const __nv_bfloat16* __restrict__ WloF,
    const __nv_bfloat16* __restrict__ WhiB, const __nv_bfloat16* __restrict__ WloB,
    const float* __restrict__ biasF, const float* __restrict__ biasB,
    float* __restrict__ Cf, float* __restrict__ Cb,
    int K, int Tcur, const unsigned char* __restrict__ mask) {
    __shared__ __align__(16) __nv_bfloat16 a_hi[128 * 24], a_lo[128 * 24];
    __shared__ __align__(16) __nv_bfloat16 w_hi[16 * 264], w_lo[16 * 264];

    const int dir = blockIdx.z;
    const int rev = dir;
    const __nv_bfloat16* Whi = dir ? WhiB : WhiF;
    const __nv_bfloat16* Wlo = dir ? WloB : WloF;
    const float* bias = dir ? biasB : biasF;
    float* C = dir ? Cb : Cf;

    const int tid  = threadIdx.x;
    const int lane = tid & 31, wid = tid >> 5;
    const int g = lane >> 2, t4 = lane & 3;
    const int warpM = wid & 3, warpN = wid >> 2;
    const int m0 = blockIdx.y << 7, n0 = blockIdx.x << 8;

    // ---- masked-tile skip (rows m0..m0+127 are one batch, contiguous t) ----
    {
        const int b  = m0 / Tcur;
        const int t0 = m0 - b * Tcur;
        const int ttmin = rev ? (Tcur - 128 - t0) : t0;
        if (mask[b * Tcur + ttmin] == 0) return;
    }

    // fill assignments
    const int ar = tid >> 1;           // A row 0..127
    const int ak = (tid & 1) << 3;     // k offset 0/8
    const int wk = tid >> 4;           // W k row 0..15
    const int wc = (tid & 15) << 4;    // W col 0..240

    const __nv_bfloat16 *pAh, *pAl;
    {
        int m  = m0 + ar;
        int bi = m / Tcur;
        int t  = m - bi * Tcur;
        int tt = rev ? (Tcur - 1 - t) : t;
        size_t base = ((size_t)bi * Tcur + tt) * lda + ak;
        pAh = Ahi + base; pAl = Alo + base;
    }
    const __nv_bfloat16* pWh = Whi + (size_t)wk * 1536 + n0 + wc;
    const __nv_bfloat16* pWl = Wlo + (size_t)wk * 1536 + n0 + wc;

    // ldmatrix lane addresses (bytes)
    const int aRowL = warpM * 32 + (lane & 15);
    const int aKofL = (lane & 16) >> 1;             // 0 or 8
    const unsigned int aHiAddr = smaddr(a_hi) + (unsigned)((aRowL * 24 + aKofL) * 2);
    const unsigned int aLoAddr = smaddr(a_lo) + (unsigned)((aRowL * 24 + aKofL) * 2);
    const int bCol = warpN * 128 + ((lane & 16) >> 1);   // col-group select
    const unsigned int bHiAddr = smaddr(w_hi) + (unsigned)(((lane & 15) * 264 + bCol) * 2);
    const unsigned int bLoAddr = smaddr(w_lo) + (unsigned)(((lane & 15) * 264 + bCol) * 2);

    float c_[2][16][4];
    #pragma unroll
    for (int mt = 0; mt < 2; ++mt)
        #pragma unroll
        for (int nt = 0; nt < 16; ++nt)
            #pragma unroll
            for (int i = 0; i < 4; ++i) c_[mt][nt][i] = 0.f;

    const int NT = K >> 4;
    uint4 rAh = *(const uint4*)pAh;
    uint4 rAl = *(const uint4*)pAl;
    uint4 rWh0 = *(const uint4*)pWh;
    uint4 rWh1 = *(const uint4*)(pWh + 8);
    uint4 rWl0 = *(const uint4*)pWl;
    uint4 rWl1 = *(const uint4*)(pWl + 8);

    for (int kt = 0; kt < NT; ++kt) {
        *(uint4*)(a_hi + ar * 24 + ak) = rAh;
        *(uint4*)(a_lo + ar * 24 + ak) = rAl;
        *(uint4*)(w_hi + wk * 264 + wc)     = rWh0;
        *(uint4*)(w_hi + wk * 264 + wc + 8) = rWh1;
        *(uint4*)(w_lo + wk * 264 + wc)     = rWl0;
        *(uint4*)(w_lo + wk * 264 + wc + 8) = rWl1;
        __syncthreads();

        if (kt + 1 < NT) {
            int k0 = (kt + 1) << 4;
            rAh = *(const uint4*)(pAh + k0);
            rAl = *(const uint4*)(pAl + k0);
            const __nv_bfloat16* qh = pWh + (size_t)k0 * 1536;
            const __nv_bfloat16* ql = pWl + (size_t)k0 * 1536;
            rWh0 = *(const uint4*)qh; rWh1 = *(const uint4*)(qh + 8);
            rWl0 = *(const uint4*)ql; rWl1 = *(const uint4*)(ql + 8);
        }

        unsigned int afh[2][4], afl[2][4];
        #pragma unroll
        for (int mt = 0; mt < 2; ++mt) {
            LDSM4(afh[mt], aHiAddr + mt * 768);
            LDSM4(afl[mt], aLoAddr + mt * 768);
        }

        #pragma unroll
        for (int p = 0; p < 8; ++p) {
            unsigned int bh[4], bl[4];
            LDSM4T(bh, bHiAddr + p * 32);
            LDSM4T(bl, bLoAddr + p * 32);
            #pragma unroll
            for (int s = 0; s < 2; ++s) {
                const int nt = 2 * p + s;
                #pragma unroll
                for (int mt = 0; mt < 2; ++mt) {
                    MMA_BF16(c_[mt][nt], afh[mt], bh[2 * s], bh[2 * s + 1]);
                    MMA_BF16(c_[mt][nt], afh[mt], bl[2 * s], bl[2 * s + 1]);
                    MMA_BF16(c_[mt][nt], afl[mt], bh[2 * s], bh[2 * s + 1]);
                }
            }
        }
        __syncthreads();
    }

    // epilogue: bias + store
    #pragma unroll
    for (int nt = 0; nt < 16; ++nt) {
        int col = n0 + warpN * 128 + nt * 8 + t4 * 2;
        float bx = __ldg(bias + col);
        float by = __ldg(bias + col + 1);
        #pragma unroll
        for (int mt = 0; mt < 2; ++mt) {
            int r = m0 + warpM * 32 + mt * 16 + g;
            float2 o0 = {c_[mt][nt][0] + bx, c_[mt][nt][1] + by};
            float2 o1 = {c_[mt][nt][2] + bx, c_[mt][nt][3] + by};
            *(float2*)(C + (size_t)r * 1536 + col)       = o0;
            *(float2*)(C + (size_t)(r + 8) * 1536 + col) = o1;
        }
    }
}

// ============================================================================
// Recurrence: persistent flag-synced kernel. 128 CTAs (64/dir), 1 CTA/SM.
// Early flag release (y stores / bf16 conversion off the critical path).
// Also derives the next layer's mask inline (dir0, CTA0, c8==0 threads).
// ============================================================================
#define REC_SMEM ((24 * 516 + 32 * 516) * 4)

__global__ void __launch_bounds__(REC_THREADS, 1) gru_rec_kernel(
    const float* __restrict__ xzf, const float* __restrict__ xzb,
    const float* __restrict__ rkf, const float* __restrict__ rkb,
    const float* __restrict__ bf,  const float* __restrict__ bb,
    const unsigned char* __restrict__ mask,
    float* __restrict__ y32,
    __nv_bfloat16* __restrict__ yhi, __nv_bfloat16* __restrict__ ylo,
    unsigned char* __restrict__ nextmask,
    int T, int flagBase, int writeHidden, float* __restrict__ hiddenOut) {
    extern __shared__ float sm[];
    float* sh_w = sm;               // [24][516]
    float* sh_h = sm + 24 * 516;    // [32][516]

    const int tid = threadIdx.x;
    const int dir = blockIdx.x >> 6;
    const int j   = blockIdx.x & 63;
    const int cb  = j << 3;
    const int b   = tid >> 3;
    const int c8  = tid & 7;
    const int col = cb + c8;

    const float* xz = dir ? xzb : xzf;
    const float* rk = dir ? rkb : rkf;
    const float* bi = (dir ? bb : bf) + 1536;

    for (int idx = tid; idx < 512 * 24; idx += REC_THREADS) {
        int k  = idx / 24;
        int gc = idx - k * 24;
        sh_w[gc * 516 + k] = __ldg(rk + (size_t)k * 1536 + (gc >> 3) * 512 + cb + (gc & 7));
    }
    const float bz = __ldg(bi + col);
    const float br = __ldg(bi + 512 + col);
    const float bh = __ldg(bi + 1024 + col);
    __syncthreads();

    const float* wz = sh_w + (0 * 8 + c8) * 516;
    const float* wr = sh_w + (1 * 8 + c8) * 516;
    const float* wh = sh_w + (2 * 8 + c8) * 516;
    const float* hrow = sh_h + b * 516;

    unsigned int* myflag = g_flag + dir * 512 + j * 8;
    const unsigned int* pollflag = g_flag + dir * 512 + (tid & 63) * 8;
    const bool maskWriter = (nextmask != nullptr) && (dir == 0) && (j == 0) && (c8 == 0);
    unsigned char mprev = 0;

    for (int t = 0; t < T; ++t) {
        const int tsrc = dir ? (T - 1 - t) : t;
        const size_t xoff = ((size_t)b * T + t) * 1536;
        const float x0 = __ldg(xz + xoff + col);
        const float x1 = __ldg(xz + xoff + 512 + col);
        const float x2 = __ldg(xz + xoff + 1024 + col);
        const unsigned char m = mask[b * T + tsrc];

        unsigned long long az = 0ULL, ar2 = 0ULL, ah = 0ULL;
        float hp = 0.f;

        if (t > 0) {
            if (tid < 64) {
                unsigned int v;
                unsigned int target = (unsigned int)(flagBase + t);
                do {
                    asm volatile("ld.acquire.gpu.global.u32 %0, [%1];"
                                 : "=r"(v) : "l"(pollflag) : "memory");
                } while (v < target);
            }
            __syncthreads();

            const float* hsrc = g_h + ((((size_t)(t & 1)) * 2 + dir) << 14);

            float4 hv[4];
            #pragma unroll
            for (int q = 0; q < 4; ++q) {
                int f = q * 256 + tid;
                int bb2 = f >> 5, kq = f & 31;
                hv[q] = __ldcg((const float4*)(hsrc + (bb2 << 9) + kq * 4));
            }

            #pragma unroll
            for (int c = 0; c < 4; ++c) {
                #pragma unroll
                for (int q = 0; q < 4; ++q) {
                    int f = q * 256 + tid;
                    int bb2 = f >> 5, kq = f & 31;
                    *(float4*)(sh_h + bb2 * 516 + c * 128 + kq * 4) = hv[q];
                }
                __syncthreads();
                if (c < 3) {
                    #pragma unroll
                    for (int q = 0; q < 4; ++q) {
                        int f = q * 256 + tid;
                        int bb2 = f >> 5, kq = f & 31;
                        hv[q] = __ldcg((const float4*)(hsrc + (bb2 << 9) + (c + 1) * 128 + kq * 4));
                    }
                }
                const int kbeg = c * 128;
                #pragma unroll 8
                for (int k = kbeg; k < kbeg + 128; k += 4) {
                    ulonglong2 h2 = *(const ulonglong2*)(hrow + k);
                    ulonglong2 z2 = *(const ulonglong2*)(wz + k);
                    ulonglong2 r2 = *(const ulonglong2*)(wr + k);
                    ulonglong2 c2 = *(const ulonglong2*)(wh + k);
                    fma2(az,  h2.x, z2.x); fma2(az,  h2.y, z2.y);
                    fma2(ar2, h2.x, r2.x); fma2(ar2, h2.y, r2.y);
                    fma2(ah,  h2.x, c2.x); fma2(ah,  h2.y, c2.y);
                }
            }
            hp = hrow[col];
        }

        const float iz = lo2(az)  + hi2(az)  + bz;
        const float ir = lo2(ar2) + hi2(ar2) + br;
        const float ic = lo2(ah)  + hi2(ah)  + bh;

        const float zg = 1.f / (1.f + expf(-(x0 + iz)));
        const float rg = 1.f / (1.f + expf(-(x1 + ir)));
        const float hh = tanhf(x2 + rg * ic);
        const float hn = zg * hp + (1.f - zg) * hh;
        const float hsel = m ? hn : hp;
        const float yval = m ? hn : 0.f;

        // ---- critical path: publish h + flag first ----
        float* hdst = g_h + ((((size_t)((t + 1) & 1)) * 2 + dir) << 14);
        hdst[(b << 9) + col] = hsel;
        __syncthreads();
        if (tid == 0) {
            unsigned int v = (unsigned int)(flagBase + t + 1);
            asm volatile("st.release.gpu.global.u32 [%0], %1;"
                         :: "l"(myflag), "r"(v) : "memory");
        }

        // ---- off critical path: outputs ----
        const size_t yidx = ((size_t)b * T + tsrc) * 1024 + (dir << 9) + col;
        if (yhi) {
            __nv_bfloat16 h16 = __float2bfloat16(yval);
            yhi[yidx] = h16;
            ylo[yidx] = __float2bfloat16(yval - __bfloat162float(h16));
        }
        if (y32) y32[yidx] = yval;
        if (writeHidden && t == T - 1)
            hiddenOut[(b << 10) + (dir << 9) + col] = hsel;
        if (maskWriter) {
            if ((t & 1) == 0) mprev = m;
            else nextmask[b * (T >> 1) + (t >> 1)] = (unsigned char)(mprev | m);
        }
    }
}

// ============================================================================
// Launch sequence (graph-capturable). Order puts layer-1 GEMM at launch #4
// (prep, G0, R0, G1, R1, G2, R2, G3, R3) for ncu capture.
// ============================================================================
extern "C" void kernel_launch(void* const* d_in, const int* in_sizes, int n_in,
                              void* d_out, int out_size) {
    (void)in_sizes; (void)n_in; (void)out_size;
    const float* inputs = (const float*)d_in[0];

    const float *k_[4][2], *r_[4][2], *bi_[4][2];
    for (int l = 0; l < 4; ++l)
        for (int d = 0; d < 2; ++d) {
            int base = 3 + l * 6 + d * 3;
            k_[l][d]  = (const float*)d_in[base + 0];
            r_[l][d]  = (const float*)d_in[base + 1];
            bi_[l][d] = (const float*)d_in[base + 2];
        }

    float *xzf, *xzb;
    unsigned char* mk;
    __nv_bfloat16 *whi, *wlo, *inhi, *inlo, *yh0, *yl0, *yh1, *yl1;
    cudaGetSymbolAddress((void**)&xzf, g_xzf);
    cudaGetSymbolAddress((void**)&xzb, g_xzb);
    cudaGetSymbolAddress((void**)&mk, g_mask);
    cudaGetSymbolAddress((void**)&whi, g_whi);
    cudaGetSymbolAddress((void**)&wlo, g_wlo);
    cudaGetSymbolAddress((void**)&inhi, g_inhi);
    cudaGetSymbolAddress((void**)&inlo, g_inlo);
    cudaGetSymbolAddress((void**)&yh0, g_yh0);
    cudaGetSymbolAddress((void**)&yl0, g_yl0);
    cudaGetSymbolAddress((void**)&yh1, g_yh1);
    cudaGetSymbolAddress((void**)&yl1, g_yl1);

    cudaFuncSetAttribute(gru_rec_kernel,
                         cudaFuncAttributeMaxDynamicSharedMemorySize, REC_SMEM);

    float* outp = (float*)d_out;
    float* hid  = outp + (size_t)32 * 128 * 1024;

    prep_kernel<<<2048, 256>>>(inputs, k_[0][0], k_[0][1], k_[1][0], k_[1][1],
                               k_[2][0], k_[2][1], k_[3][0], k_[3][1]);

    const int Ts[4]   = {1024, 512, 256, 128};
    const int Ks[4]   = {240, 2048, 2048, 2048};
    const int ldas[4] = {240, 2048, 2048, 2048};
    const int woff[4][2] = {{0, WSZ0},
                            {2 * WSZ0, 2 * WSZ0 + WSZ1},
                            {2 * WSZ0 + 2 * WSZ1, 2 * WSZ0 + 3 * WSZ1},
                            {2 * WSZ0 + 4 * WSZ1, 2 * WSZ0 + 5 * WSZ1}};
    const int moff[4]  = {0, 32768, 49152, 57344};
    const int fbase[4] = {0, 1024, 1536, 1792};

    const __nv_bfloat16* Ah[4] = {inhi, yh0, yh1, yh0};
    const __nv_bfloat16* Al[4] = {inlo, yl0, yl1, yl0};
    __nv_bfloat16* Yh[4] = {yh0, yh1, yh0, nullptr};
    __nv_bfloat16* Yl[4] = {yl0, yl1, yl0, nullptr};
    float* Y32[4] = {nullptr, nullptr, nullptr, outp};

    for (int l = 0; l < 4; ++l) {
        const int T = Ts[l], K = Ks[l];
        const int rows = 32 * T;

        dim3 grid(6, rows / 128, 2);
        gemm_xz<<<grid, 256>>>(Ah[l], Al[l], ldas[l],
                               whi + woff[l][0], wlo + woff[l][0],
                               whi + woff[l][1], wlo + woff[l][1],
                               bi_[l][0], bi_[l][1],
                               xzf, xzb, K, T, mk + moff[l]);

        gru_rec_kernel<<<128, REC_THREADS, REC_SMEM>>>(
            xzf, xzb, r_[l][0], r_[l][1], bi_[l][0], bi_[l][1],
            mk + moff[l], Y32[l], Yh[l], Yl[l],
            (l < 3) ? (mk + moff[l + 1]) : nullptr,
            T, fbase[l], (l == 3) ? 1 : 0, hid);
    }
}

// round 6
// speedup vs baseline: 2.3489x; 1.8330x over previous
#include <cuda_runtime.h>
#include <cuda_bf16.h>
#include <cstdint>

// ============================================================================
// 4-layer pyramidal BiGRU. B=32, H=512, 3H=1536.
// Layers l=0..3: T = 1024,512,256,128 ; din = 240,2048,2048,2048
// ============================================================================

#define REC_THREADS 256

// ---------------- static device scratch ----------------
__device__ float g_xzf[50331648];                 // [32][1024][1536] max
__device__ float g_xzb[50331648];
__device__ unsigned int g_flag[2 * 512];          // [dir][64 ctas] stride-8
__device__ unsigned char g_mask[65536];           // per-layer offsets
__device__ __nv_bfloat16 g_whi[19611648], g_wlo[19611648];
__device__ __nv_bfloat16 g_inhi[7864320],  g_inlo[7864320];
__device__ __nv_bfloat16 g_yh0[33554432],  g_yl0[33554432];
__device__ __nv_bfloat16 g_yh1[16777216],  g_yl1[16777216];
// hidden state exchange, bf16 hi/lo, [parity][dir][32][512]
__device__ __nv_bfloat16 g_hhi[4 * 16384], g_hlo[4 * 16384];

// ---------------- mma / ldmatrix ----------------
#define MMA_BF16(c, a, b0, b1)                                              \
    asm volatile("mma.sync.aligned.m16n8k16.row.col.f32.bf16.bf16.f32 "     \
        "{%0,%1,%2,%3}, {%4,%5,%6,%7}, {%8,%9}, {%0,%1,%2,%3};"             \
        : "+f"((c)[0]), "+f"((c)[1]), "+f"((c)[2]), "+f"((c)[3])            \
        : "r"((a)[0]), "r"((a)[1]), "r"((a)[2]), "r"((a)[3]),               \
          "r"(b0), "r"(b1))

#define LDSM4(R, addr)                                                      \
    asm volatile("ldmatrix.sync.aligned.m8n8.x4.shared.b16 "                \
        "{%0,%1,%2,%3}, [%4];"                                              \
        : "=r"((R)[0]), "=r"((R)[1]), "=r"((R)[2]), "=r"((R)[3])            \
        : "r"(addr))

#define LDSM4T(R, addr)                                                     \
    asm volatile("ldmatrix.sync.aligned.m8n8.x4.trans.shared.b16 "          \
        "{%0,%1,%2,%3}, [%4];"                                              \
        : "=r"((R)[0]), "=r"((R)[1]), "=r"((R)[2]), "=r"((R)[3])            \
        : "r"(addr))

__device__ __forceinline__ unsigned int smaddr(const void* p) {
    return (unsigned int)__cvta_generic_to_shared(p);
}
__device__ __forceinline__ unsigned int bfpack(float a, float b) {
    __nv_bfloat162 h = __floats2bfloat162_rn(a, b);
    return *reinterpret_cast<unsigned int*>(&h);
}

// ============================================================================
// prep kernel: convert 8 weight matrices + layer-0 input to bf16 hi/lo,
// compute layer-0 mask, zero flags.
// ============================================================================
__device__ __forceinline__ void cvt4(float4 v, uint2& hi, uint2& lo) {
    __nv_bfloat162 h0 = __floats2bfloat162_rn(v.x, v.y);
    __nv_bfloat162 h1 = __floats2bfloat162_rn(v.z, v.w);
    float2 f0 = __bfloat1622float2(h0);
    float2 f1 = __bfloat1622float2(h1);
    __nv_bfloat162 l0 = __floats2bfloat162_rn(v.x - f0.x, v.y - f0.y);
    __nv_bfloat162 l1 = __floats2bfloat162_rn(v.z - f1.x, v.w - f1.y);
    hi.x = *(unsigned int*)&h0; hi.y = *(unsigned int*)&h1;
    lo.x = *(unsigned int*)&l0; lo.y = *(unsigned int*)&l1;
}

#define WSZ0 368640
#define WSZ1 3145728

__global__ void prep_kernel(const float* __restrict__ in,
                            const float* w0, const float* w1, const float* w2,
                            const float* w3, const float* w4, const float* w5,
                            const float* w6, const float* w7) {
    const float* ws[8] = {w0, w1, w2, w3, w4, w5, w6, w7};
    const int sz[8]  = {WSZ0, WSZ0, WSZ1, WSZ1, WSZ1, WSZ1, WSZ1, WSZ1};
    const int off[8] = {0, WSZ0, 2 * WSZ0, 2 * WSZ0 + WSZ1, 2 * WSZ0 + 2 * WSZ1,
                        2 * WSZ0 + 3 * WSZ1, 2 * WSZ0 + 4 * WSZ1, 2 * WSZ0 + 5 * WSZ1};
    const int gid = blockIdx.x * blockDim.x + threadIdx.x;
    const int stride = gridDim.x * blockDim.x;

    #pragma unroll 1
    for (int w = 0; w < 8; ++w) {
        const float4* W = (const float4*)ws[w];
        uint2* hi = (uint2*)(g_whi + off[w]);
        uint2* lo = (uint2*)(g_wlo + off[w]);
        int n4 = sz[w] >> 2;
        for (int i = gid; i < n4; i += stride) {
            uint2 h, l; cvt4(__ldg(W + i), h, l);
            hi[i] = h; lo[i] = l;
        }
    }
    {
        const float4* X = (const float4*)in;
        uint2* hi = (uint2*)g_inhi; uint2* lo = (uint2*)g_inlo;
        for (int i = gid; i < (7864320 >> 2); i += stride) {
            uint2 h, l; cvt4(__ldg(X + i), h, l);
            hi[i] = h; lo[i] = l;
        }
    }
    for (int r = gid; r < 32768; r += stride) {
        const float4* p = (const float4*)(in + (size_t)r * 240);
        bool any = false;
        for (int i = 0; i < 60; ++i) {
            float4 v = __ldg(p + i);
            any = any | (v.x != 0.f) | (v.y != 0.f) | (v.z != 0.f) | (v.w != 0.f);
            if (any) break;
        }
        g_mask[r] = any ? 1 : 0;
    }
    for (int i = gid; i < 2 * 512; i += stride) g_flag[i] = 0u;
}

// ============================================================================
// Input-projection GEMM (unchanged from round 5): bf16 hi/lo, mma.sync,
// tile 128x256x16, merged fwd/bwd via grid.z, masked-tile skip.
// ============================================================================
__global__ void __launch_bounds__(256, 1) gemm_xz(
    const __nv_bfloat16* __restrict__ Ahi, const __nv_bfloat16* __restrict__ Alo,
    int lda,
    const __nv_bfloat16* __restrict__ WhiF, const __nv_bfloat16* __restrict__ WloF,
    const __nv_bfloat16* __restrict__ WhiB, const __nv_bfloat16* __restrict__ WloB,
    const float* __restrict__ biasF, const float* __restrict__ biasB,
    float* __restrict__ Cf, float* __restrict__ Cb,
    int K, int Tcur, const unsigned char* __restrict__ mask) {
    __shared__ __align__(16) __nv_bfloat16 a_hi[128 * 24], a_lo[128 * 24];
    __shared__ __align__(16) __nv_bfloat16 w_hi[16 * 264], w_lo[16 * 264];

    const int dir = blockIdx.z;
    const int rev = dir;
    const __nv_bfloat16* Whi = dir ? WhiB : WhiF;
    const __nv_bfloat16* Wlo = dir ? WloB : WloF;
    const float* bias = dir ? biasB : biasF;
    float* C = dir ? Cb : Cf;

    const int tid  = threadIdx.x;
    const int lane = tid & 31, wid = tid >> 5;
    const int g = lane >> 2, t4 = lane & 3;
    const int warpM = wid & 3, warpN = wid >> 2;
    const int m0 = blockIdx.y << 7, n0 = blockIdx.x << 8;

    {
        const int b  = m0 / Tcur;
        const int t0 = m0 - b * Tcur;
        const int ttmin = rev ? (Tcur - 128 - t0) : t0;
        if (mask[b * Tcur + ttmin] == 0) return;
    }

    const int ar = tid >> 1;
    const int ak = (tid & 1) << 3;
    const int wk = tid >> 4;
    const int wc = (tid & 15) << 4;

    const __nv_bfloat16 *pAh, *pAl;
    {
        int m  = m0 + ar;
        int bi = m / Tcur;
        int t  = m - bi * Tcur;
        int tt = rev ? (Tcur - 1 - t) : t;
        size_t base = ((size_t)bi * Tcur + tt) * lda + ak;
        pAh = Ahi + base; pAl = Alo + base;
    }
    const __nv_bfloat16* pWh = Whi + (size_t)wk * 1536 + n0 + wc;
    const __nv_bfloat16* pWl = Wlo + (size_t)wk * 1536 + n0 + wc;

    const int aRowL = warpM * 32 + (lane & 15);
    const int aKofL = (lane & 16) >> 1;
    const unsigned int aHiAddr = smaddr(a_hi) + (unsigned)((aRowL * 24 + aKofL) * 2);
    const unsigned int aLoAddr = smaddr(a_lo) + (unsigned)((aRowL * 24 + aKofL) * 2);
    const int bCol = warpN * 128 + ((lane & 16) >> 1);
    const unsigned int bHiAddr = smaddr(w_hi) + (unsigned)(((lane & 15) * 264 + bCol) * 2);
    const unsigned int bLoAddr = smaddr(w_lo) + (unsigned)(((lane & 15) * 264 + bCol) * 2);

    float c_[2][16][4];
    #pragma unroll
    for (int mt = 0; mt < 2; ++mt)
        #pragma unroll
        for (int nt = 0; nt < 16; ++nt)
            #pragma unroll
            for (int i = 0; i < 4; ++i) c_[mt][nt][i] = 0.f;

    const int NT = K >> 4;
    uint4 rAh = *(const uint4*)pAh;
    uint4 rAl = *(const uint4*)pAl;
    uint4 rWh0 = *(const uint4*)pWh;
    uint4 rWh1 = *(const uint4*)(pWh + 8);
    uint4 rWl0 = *(const uint4*)pWl;
    uint4 rWl1 = *(const uint4*)(pWl + 8);

    for (int kt = 0; kt < NT; ++kt) {
        *(uint4*)(a_hi + ar * 24 + ak) = rAh;
        *(uint4*)(a_lo + ar * 24 + ak) = rAl;
        *(uint4*)(w_hi + wk * 264 + wc)     = rWh0;
        *(uint4*)(w_hi + wk * 264 + wc + 8) = rWh1;
        *(uint4*)(w_lo + wk * 264 + wc)     = rWl0;
        *(uint4*)(w_lo + wk * 264 + wc + 8) = rWl1;
        __syncthreads();

        if (kt + 1 < NT) {
            int k0 = (kt + 1) << 4;
            rAh = *(const uint4*)(pAh + k0);
            rAl = *(const uint4*)(pAl + k0);
            const __nv_bfloat16* qh = pWh + (size_t)k0 * 1536;
            const __nv_bfloat16* ql = pWl + (size_t)k0 * 1536;
            rWh0 = *(const uint4*)qh; rWh1 = *(const uint4*)(qh + 8);
            rWl0 = *(const uint4*)ql; rWl1 = *(const uint4*)(ql + 8);
        }

        unsigned int afh[2][4], afl[2][4];
        #pragma unroll
        for (int mt = 0; mt < 2; ++mt) {
            LDSM4(afh[mt], aHiAddr + mt * 768);
            LDSM4(afl[mt], aLoAddr + mt * 768);
        }

        #pragma unroll
        for (int p = 0; p < 8; ++p) {
            unsigned int bh[4], bl[4];
            LDSM4T(bh, bHiAddr + p * 32);
            LDSM4T(bl, bLoAddr + p * 32);
            #pragma unroll
            for (int s = 0; s < 2; ++s) {
                const int nt = 2 * p + s;
                #pragma unroll
                for (int mt = 0; mt < 2; ++mt) {
                    MMA_BF16(c_[mt][nt], afh[mt], bh[2 * s], bh[2 * s + 1]);
                    MMA_BF16(c_[mt][nt], afh[mt], bl[2 * s], bl[2 * s + 1]);
                    MMA_BF16(c_[mt][nt], afl[mt], bh[2 * s], bh[2 * s + 1]);
                }
            }
        }
        __syncthreads();
    }

    #pragma unroll
    for (int nt = 0; nt < 16; ++nt) {
        int col = n0 + warpN * 128 + nt * 8 + t4 * 2;
        float bx = __ldg(bias + col);
        float by = __ldg(bias + col + 1);
        #pragma unroll
        for (int mt = 0; mt < 2; ++mt) {
            int r = m0 + warpM * 32 + mt * 16 + g;
            float2 o0 = {c_[mt][nt][0] + bx, c_[mt][nt][1] + by};
            float2 o1 = {c_[mt][nt][2] + bx, c_[mt][nt][3] + by};
            *(float2*)(C + (size_t)r * 1536 + col)       = o0;
            *(float2*)(C + (size_t)(r + 8) * 1536 + col) = o1;
        }
    }
}

// ============================================================================
// Recurrence on tensor cores. 128 CTAs (64/dir), 256 threads, 1 CTA/SM.
//   Per CTA per step: inner[32 b][24 cols] = h[32][512] @ rk_slice.
//   Warps 0..5 = (gate, mt): hold B fragments for all K=512 in REGISTERS
//   (preloaded once, bf16 hi/lo), ldmatrix A (h hi/lo) from SMEM, 96 mma.
//   Gate tiles -> SMEM f32 -> scalar epilogue (exact as reference).
//   h exchanged via L2 as bf16 hi/lo; own-column h carry kept exact in SMEM.
// SMEM: ahi[32][520] bf16 | alo[32][520] bf16 | gate[3][32][8] f32 | hp[32][8]
// ============================================================================
#define LDK 520
#define REC_SMEM (2 * 32 * LDK * 2 + 3 * 32 * 8 * 4 + 32 * 8 * 4)

__global__ void __launch_bounds__(REC_THREADS, 1) gru_rec_kernel(
    const float* __restrict__ xzf, const float* __restrict__ xzb,
    const float* __restrict__ rkf, const float* __restrict__ rkb,
    const float* __restrict__ bf,  const float* __restrict__ bb,
    const unsigned char* __restrict__ mask,
    float* __restrict__ y32,
    __nv_bfloat16* __restrict__ yhi, __nv_bfloat16* __restrict__ ylo,
    unsigned char* __restrict__ nextmask,
    int T, int flagBase, int writeHidden, float* __restrict__ hiddenOut) {
    extern __shared__ __align__(16) char smraw[];
    __nv_bfloat16* sh_ahi = (__nv_bfloat16*)smraw;                // [32][520]
    __nv_bfloat16* sh_alo = sh_ahi + 32 * LDK;                    // [32][520]
    float* sh_gate = (float*)(sh_alo + 32 * LDK);                 // [3][32][8]
    float* sh_hp   = sh_gate + 3 * 32 * 8;                        // [32][8]

    const int tid  = threadIdx.x;
    const int lane = tid & 31, wid = tid >> 5;
    const int dir = blockIdx.x >> 6;
    const int j   = blockIdx.x & 63;
    const int cb  = j << 3;
    const int b   = tid >> 3;       // batch 0..31 (epilogue mapping)
    const int c8  = tid & 7;
    const int col = cb + c8;

    const float* xz = dir ? xzb : xzf;
    const float* rk = dir ? rkb : rkf;
    const float* bi = (dir ? bb : bf) + 1536;   // b[1]

    // zero gate + hp buffers
    for (int i = tid; i < 3 * 256 + 256; i += REC_THREADS) sh_gate[i] = 0.f;

    // ---- B-fragment preload (warps 0..5) ----
    const int gate = wid >> 1;      // 0..2
    const int mt   = wid & 1;       // 0..1
    const int t4   = lane & 3;
    const int gcol = lane >> 2;     // 0..7
    unsigned int Bh0[32], Bh1[32], Bl0[32], Bl1[32];
    if (wid < 6) {
        const float* wcolp = rk + gate * 512 + cb + gcol;
        #pragma unroll 1
        for (int kt = 0; kt < 32; ++kt) {
            int k0 = kt * 16 + t4 * 2;
            float w00 = __ldg(wcolp + (size_t)(k0)     * 1536);
            float w01 = __ldg(wcolp + (size_t)(k0 + 1) * 1536);
            float w10 = __ldg(wcolp + (size_t)(k0 + 8) * 1536);
            float w11 = __ldg(wcolp + (size_t)(k0 + 9) * 1536);
            __nv_bfloat16 h00 = __float2bfloat16(w00), h01 = __float2bfloat16(w01);
            __nv_bfloat16 h10 = __float2bfloat16(w10), h11 = __float2bfloat16(w11);
            Bh0[kt] = ((unsigned)*(unsigned short*)&h01 << 16) | *(unsigned short*)&h00;
            Bh1[kt] = ((unsigned)*(unsigned short*)&h11 << 16) | *(unsigned short*)&h10;
            Bl0[kt] = bfpack(w00 - __bfloat162float(h00), w01 - __bfloat162float(h01));
            Bl1[kt] = bfpack(w10 - __bfloat162float(h10), w11 - __bfloat162float(h11));
        }
    }
    const float bz = __ldg(bi + col);
    const float br = __ldg(bi + 512 + col);
    const float bh = __ldg(bi + 1024 + col);
    __syncthreads();

    // ldmatrix lane address (A = h matrix, rows = batch)
    const unsigned int aBase = smaddr(sh_ahi) +
        (unsigned)(((mt * 16 + (lane & 15)) * LDK + ((lane >> 4) << 3)) * 2);
    const unsigned int aLoBase = aBase + 32 * LDK * 2;

    unsigned int* myflag = g_flag + dir * 512 + j * 8;
    const unsigned int* pollflag = g_flag + dir * 512 + (tid & 63) * 8;
    const bool maskWriter = (nextmask != nullptr) && (dir == 0) && (j == 0) && (c8 == 0);
    unsigned char mprev = 0;

    for (int t = 0; t < T; ++t) {
        const int tsrc = dir ? (T - 1 - t) : t;
        const size_t xoff = ((size_t)b * T + t) * 1536;
        const float x0 = __ldg(xz + xoff + col);
        const float x1 = __ldg(xz + xoff + 512 + col);
        const float x2 = __ldg(xz + xoff + 1024 + col);
        const unsigned char m = mask[b * T + tsrc];

        if (t > 0) {
            // ---- wait for step t-1 of all CTAs in this direction ----
            if (tid < 64) {
                unsigned int v;
                unsigned int target = (unsigned int)(flagBase + t);
                do {
                    asm volatile("ld.acquire.gpu.global.u32 %0, [%1];"
                                 : "=r"(v) : "l"(pollflag) : "memory");
                } while (v < target);
            }
            __syncthreads();

            // ---- stage h (bf16 hi/lo, 32KB each) into SMEM ----
            const size_t hsrc = (size_t)(((t & 1) * 2 + dir)) << 14;
            const __nv_bfloat16* ghi = g_hhi + hsrc;
            const __nv_bfloat16* glo = g_hlo + hsrc;
            #pragma unroll
            for (int q = 0; q < 8; ++q) {
                int v = q * 256 + tid;              // uint4 index, 0..2047
                int bb2 = v >> 6, kc = v & 63;      // row, 8-elem chunk
                uint4 hv = __ldcg((const uint4*)(ghi + (bb2 << 9) + kc * 8));
                uint4 lv = __ldcg((const uint4*)(glo + (bb2 << 9) + kc * 8));
                *(uint4*)(sh_ahi + bb2 * LDK + kc * 8) = hv;
                *(uint4*)(sh_alo + bb2 * LDK + kc * 8) = lv;
            }
            __syncthreads();

            // ---- mma warps: 32 kt x (2 ldmatrix + 3 mma) ----
            if (wid < 6) {
                float acc[4][4];
                #pragma unroll
                for (int i = 0; i < 4; ++i)
                    #pragma unroll
                    for (int q = 0; q < 4; ++q) acc[i][q] = 0.f;
                #pragma unroll
                for (int kt = 0; kt < 32; ++kt) {
                    unsigned int ah[4], al[4];
                    LDSM4(ah, aBase + kt * 32);
                    LDSM4(al, aLoBase + kt * 32);
                    float* c = acc[kt & 3];
                    MMA_BF16(c, ah, Bh0[kt], Bh1[kt]);
                    MMA_BF16(c, ah, Bl0[kt], Bl1[kt]);
                    MMA_BF16(c, al, Bh0[kt], Bh1[kt]);
                }
                float c0 = acc[0][0] + acc[1][0] + acc[2][0] + acc[3][0];
                float c1 = acc[0][1] + acc[1][1] + acc[2][1] + acc[3][1];
                float c2 = acc[0][2] + acc[1][2] + acc[2][2] + acc[3][2];
                float c3 = acc[0][3] + acc[1][3] + acc[2][3] + acc[3][3];
                const int row = lane >> 2, cq = (lane & 3) << 1;
                float* gp = sh_gate + gate * 256 + (mt * 16 + row) * 8 + cq;
                gp[0] = c0; gp[1] = c1;
                gp[64] = c2; gp[65] = c3;           // row+8 => +8*8 floats
            }
            __syncthreads();
        }

        // ---- scalar epilogue: exact reference math ----
        const float iz = sh_gate[0 * 256 + b * 8 + c8] + bz;
        const float ir = sh_gate[1 * 256 + b * 8 + c8] + br;
        const float ic = sh_gate[2 * 256 + b * 8 + c8] + bh;

        const float zg = 1.f / (1.f + expf(-(x0 + iz)));
        const float rg = 1.f / (1.f + expf(-(x1 + ir)));
        const float hh = tanhf(x2 + rg * ic);
        const float hp = sh_hp[b * 8 + c8];
        const float hn = zg * hp + (1.f - zg) * hh;
        const float hsel = m ? hn : hp;
        const float yval = m ? hn : 0.f;
        sh_hp[b * 8 + c8] = hsel;

        // ---- critical path: publish h (bf16 hi/lo) + flag ----
        const size_t hdst = (size_t)((((t + 1) & 1) * 2 + dir)) << 14;
        __nv_bfloat16 h16 = __float2bfloat16(hsel);
        __nv_bfloat16 l16 = __float2bfloat16(hsel - __bfloat162float(h16));
        g_hhi[hdst + (b << 9) + col] = h16;
        g_hlo[hdst + (b << 9) + col] = l16;
        __syncthreads();
        if (tid == 0) {
            unsigned int v = (unsigned int)(flagBase + t + 1);
            asm volatile("st.release.gpu.global.u32 [%0], %1;"
                         :: "l"(myflag), "r"(v) : "memory");
        }

        // ---- off critical path: outputs ----
        const size_t yidx = ((size_t)b * T + tsrc) * 1024 + (dir << 9) + col;
        if (yhi) {
            __nv_bfloat16 yh16 = __float2bfloat16(yval);
            yhi[yidx] = yh16;
            ylo[yidx] = __float2bfloat16(yval - __bfloat162float(yh16));
        }
        if (y32) y32[yidx] = yval;
        if (writeHidden && t == T - 1)
            hiddenOut[(b << 10) + (dir << 9) + col] = hsel;
        if (maskWriter) {
            if ((t & 1) == 0) mprev = m;
            else nextmask[b * (T >> 1) + (t >> 1)] = (unsigned char)(mprev | m);
        }
    }
}

// ============================================================================
// Launch sequence (graph-capturable)
// ============================================================================
extern "C" void kernel_launch(void* const* d_in, const int* in_sizes, int n_in,
                              void* d_out, int out_size) {
    (void)in_sizes; (void)n_in; (void)out_size;
    const float* inputs = (const float*)d_in[0];

    const float *k_[4][2], *r_[4][2], *bi_[4][2];
    for (int l = 0; l < 4; ++l)
        for (int d = 0; d < 2; ++d) {
            int base = 3 + l * 6 + d * 3;
            k_[l][d]  = (const float*)d_in[base + 0];
            r_[l][d]  = (const float*)d_in[base + 1];
            bi_[l][d] = (const float*)d_in[base + 2];
        }

    float *xzf, *xzb;
    unsigned char* mk;
    __nv_bfloat16 *whi, *wlo, *inhi, *inlo, *yh0, *yl0, *yh1, *yl1;
    cudaGetSymbolAddress((void**)&xzf, g_xzf);
    cudaGetSymbolAddress((void**)&xzb, g_xzb);
    cudaGetSymbolAddress((void**)&mk, g_mask);
    cudaGetSymbolAddress((void**)&whi, g_whi);
    cudaGetSymbolAddress((void**)&wlo, g_wlo);
    cudaGetSymbolAddress((void**)&inhi, g_inhi);
    cudaGetSymbolAddress((void**)&inlo, g_inlo);
    cudaGetSymbolAddress((void**)&yh0, g_yh0);
    cudaGetSymbolAddress((void**)&yl0, g_yl0);
    cudaGetSymbolAddress((void**)&yh1, g_yh1);
    cudaGetSymbolAddress((void**)&yl1, g_yl1);

    cudaFuncSetAttribute(gru_rec_kernel,
                         cudaFuncAttributeMaxDynamicSharedMemorySize, REC_SMEM);

    float* outp = (float*)d_out;
    float* hid  = outp + (size_t)32 * 128 * 1024;

    prep_kernel<<<2048, 256>>>(inputs, k_[0][0], k_[0][1], k_[1][0], k_[1][1],
                               k_[2][0], k_[2][1], k_[3][0], k_[3][1]);

    const int Ts[4]   = {1024, 512, 256, 128};
    const int Ks[4]   = {240, 2048, 2048, 2048};
    const int ldas[4] = {240, 2048, 2048, 2048};
    const int woff[4][2] = {{0, WSZ0},
                            {2 * WSZ0, 2 * WSZ0 + WSZ1},
                            {2 * WSZ0 + 2 * WSZ1, 2 * WSZ0 + 3 * WSZ1},
                            {2 * WSZ0 + 4 * WSZ1, 2 * WSZ0 + 5 * WSZ1}};
    const int moff[4]  = {0, 32768, 49152, 57344};
    const int fbase[4] = {0, 1024, 1536, 1792};

    const __nv_bfloat16* Ah[4] = {inhi, yh0, yh1, yh0};
    const __nv_bfloat16* Al[4] = {inlo, yl0, yl1, yl0};
    __nv_bfloat16* Yh[4] = {yh0, yh1, yh0, nullptr};
    __nv_bfloat16* Yl[4] = {yl0, yl1, yl0, nullptr};
    float* Y32[4] = {nullptr, nullptr, nullptr, outp};

    for (int l = 0; l < 4; ++l) {
        const int T = Ts[l], K = Ks[l];
        const int rows = 32 * T;

        dim3 grid(6, rows / 128, 2);
        gemm_xz<<<grid, 256>>>(Ah[l], Al[l], ldas[l],
                               whi + woff[l][0], wlo + woff[l][0],
                               whi + woff[l][1], wlo + woff[l][1],
                               bi_[l][0], bi_[l][1],
                               xzf, xzb, K, T, mk + moff[l]);

        gru_rec_kernel<<<128, REC_THREADS, REC_SMEM>>>(
            xzf, xzb, r_[l][0], r_[l][1], bi_[l][0], bi_[l][1],
            mk + moff[l], Y32[l], Yh[l], Yl[l],
            (l < 3) ? (mk + moff[l + 1]) : nullptr,
            T, fbase[l], (l == 3) ? 1 : 0, hid);
    }
}